// round 14
// baseline (speedup 1.0000x reference)
#include <cuda_runtime.h>
#include <cuda_bf16.h>
#include <math.h>
#include <stdint.h>

#define BB 2
#define SS 2048
#define HH 16
#define DD 128
#define HIDN 2048
#define BHS (BB*HH*SS)
#define MTOT 4096

// ---------------- scratch ----------------
__device__ float g_v  [BB*HH*SS*DD];
__device__ float g_sq [BB*HH*SS*DD];
__device__ float g_sk [BB*HH*SS*DD];
__device__ float g_mem[BB*HH*SS*DD];
__device__ float g_att[BB*HH*SS*DD];
__device__ float g_den[BHS];
__device__ float g_mpart[HH*16*DD*DD];
__device__ float g_zpart[HH*16*DD];

__device__ __nv_bfloat16 g_AH[MTOT*HIDN];
__device__ __nv_bfloat16 g_AL[MTOT*HIDN];
__device__ __nv_bfloat16 g_WtH[4u*HIDN*HIDN];
__device__ __nv_bfloat16 g_WtL[4u*HIDN*HIDN];
__device__ __nv_bfloat16 g_CH[MTOT*HIDN];
__device__ __nv_bfloat16 g_CL[MTOT*HIDN];
__device__ __nv_bfloat16 g_qH[BB*HH*SS*DD];
__device__ __nv_bfloat16 g_qL[BB*HH*SS*DD];
__device__ __nv_bfloat16 g_kH[BB*HH*SS*DD];
__device__ __nv_bfloat16 g_kL[BB*HH*SS*DD];
__device__ __nv_bfloat16 g_sqH[BB*HH*SS*DD];
__device__ __nv_bfloat16 g_sqL[BB*HH*SS*DD];
__device__ __nv_bfloat16 g_MtH[HH*DD*DD];
__device__ __nv_bfloat16 g_MtL[HH*DD*DD];
__device__ __nv_bfloat16 g_vTH[BB*HH*SS*DD];   // V^T [bh][d][s] splits
__device__ __nv_bfloat16 g_vTL[BB*HH*SS*DD];
__device__ __nv_bfloat16 g_skTH[BB*HH*SS*DD];  // sigma(k)^T [bh][d][s] splits
__device__ __nv_bfloat16 g_skTL[BB*HH*SS*DD];

// ================= mma.sync helpers =================
__device__ __forceinline__ uint32_t smem_u32(const void* p){
    return (uint32_t)__cvta_generic_to_shared(p);
}
__device__ __forceinline__ void ldsm_x4(uint32_t& r0, uint32_t& r1, uint32_t& r2, uint32_t& r3, uint32_t addr){
    asm volatile("ldmatrix.sync.aligned.m8n8.x4.shared.b16 {%0,%1,%2,%3}, [%4];"
        : "=r"(r0), "=r"(r1), "=r"(r2), "=r"(r3) : "r"(addr));
}
__device__ __forceinline__ void ldsm_x2(uint32_t& r0, uint32_t& r1, uint32_t addr){
    asm volatile("ldmatrix.sync.aligned.m8n8.x2.shared.b16 {%0,%1}, [%2];"
        : "=r"(r0), "=r"(r1) : "r"(addr));
}
__device__ __forceinline__ void mma_bf16(float* d, const uint32_t* a, const uint32_t* b){
    asm volatile("mma.sync.aligned.m16n8k16.row.col.f32.bf16.bf16.f32 "
        "{%0,%1,%2,%3}, {%4,%5,%6,%7}, {%8,%9}, {%0,%1,%2,%3};"
        : "+f"(d[0]), "+f"(d[1]), "+f"(d[2]), "+f"(d[3])
        : "r"(a[0]), "r"(a[1]), "r"(a[2]), "r"(a[3]), "r"(b[0]), "r"(b[1]));
}
__device__ __forceinline__ void bf16split(float v, __nv_bfloat16& h, __nv_bfloat16& l){
    h = __float2bfloat16_rn(v);
    l = __float2bfloat16_rn(v - __bfloat162float(h));
}
__device__ __forceinline__ void cp_async16(uint32_t smem_addr, const void* gptr){
    asm volatile("cp.async.cg.shared.global [%0], [%1], 16;" :: "r"(smem_addr), "l"(gptr));
}
#define CP_COMMIT() asm volatile("cp.async.commit_group;" ::: "memory")
#define CP_WAIT1()  asm volatile("cp.async.wait_group 1;" ::: "memory")
#define CP_WAIT0()  asm volatile("cp.async.wait_group 0;" ::: "memory")

// ================= pre-pass kernels =================
__global__ __launch_bounds__(256) void split_a_kernel(const float* __restrict__ A)
{
    int idx = blockIdx.x*256 + threadIdx.x;
    __nv_bfloat16 h,l; bf16split(A[idx], h, l);
    g_AH[idx] = h; g_AL[idx] = l;
}

__global__ __launch_bounds__(256) void wsplit_kernel(
    const float* __restrict__ Wq, const float* __restrict__ Wk,
    const float* __restrict__ Wv, const float* __restrict__ Wo)
{
    __shared__ float tile[32][33];
    int z = blockIdx.z;
    const float* W = (z==0)?Wq:((z==1)?Wk:((z==2)?Wv:Wo));
    __nv_bfloat16* H = g_WtH + (size_t)z*HIDN*HIDN;
    __nv_bfloat16* L = g_WtL + (size_t)z*HIDN*HIDN;
    int n0 = blockIdx.x*32, k0 = blockIdx.y*32;
    int tx = threadIdx.x & 31, ty = threadIdx.x >> 5;
    #pragma unroll
    for (int i=0;i<4;i++)
        tile[ty+8*i][tx] = W[(size_t)(k0+ty+8*i)*HIDN + n0+tx];
    __syncthreads();
    #pragma unroll
    for (int i=0;i<4;i++){
        __nv_bfloat16 h,l; bf16split(tile[tx][ty+8*i], h, l);
        size_t o = (size_t)(n0+ty+8*i)*HIDN + k0+tx;
        H[o] = h; L[o] = l;
    }
}

__global__ __launch_bounds__(256) void msplit_kernel(const float* __restrict__ M)
{
    int idx = blockIdx.x*256 + threadIdx.x;
    int h = idx >> 14, d = (idx>>7)&127, e = idx&127;
    __nv_bfloat16 hh,ll; bf16split(M[idx], hh, ll);
    size_t o = (size_t)h*16384 + e*128 + d;
    g_MtH[o] = hh; g_MtL[o] = ll;
}

__global__ __launch_bounds__(256) void combine_split_kernel(const float* __restrict__ beta)
{
    int idx = blockIdx.x*256 + threadIdx.x;
    float g = 1.f/(1.f + expf(-beta[0]));
    int m = idx >> 11, kcol = idx & 2047;
    int b = m>>11, s = m&2047, h = kcol>>7, d = kcol&127;
    size_t a = (((size_t)(b*HH+h))*SS + s)*DD + d;
    float v = g*g_mem[a] + (1.f-g)*g_att[a];
    __nv_bfloat16 hh,ll; bf16split(v, hh, ll);
    g_CH[idx] = hh; g_CL[idx] = ll;
}

// transpose+split: [bh][s][d] fp32 -> [bh][d][s] bf16 H/L.  which: 0=V, 1=sigma(k)
#define VT_SMEM (2*128*66*4)
__global__ __launch_bounds__(256) void tsplit_kernel()
{
    extern __shared__ char sm[];
    uint32_t* sH = (uint32_t*)sm;            // [128 d][66]
    uint32_t* sL = sH + 128*66;
    int bh = blockIdx.x, sc0 = blockIdx.y*128;
    int which = blockIdx.z;
    const float* src = which ? g_sk : g_v;
    __nv_bfloat16* dH = which ? g_skTH : g_vTH;
    __nv_bfloat16* dL = which ? g_skTL : g_vTL;
    int t = threadIdx.x;
    size_t base = ((size_t)bh*SS + sc0)*DD;
    #pragma unroll
    for (int i=0;i<32;i++){
        int pidx = i*256 + t;
        int d = pidx & 127, sp = pidx >> 7;
        float v0 = src[base + (size_t)(2*sp)*DD + d];
        float v1 = src[base + (size_t)(2*sp+1)*DD + d];
        __nv_bfloat16 h0,l0,h1,l1;
        bf16split(v0,h0,l0); bf16split(v1,h1,l1);
        uint32_t ph = ((uint32_t)__bfloat16_as_ushort(h1)<<16) | (uint32_t)__bfloat16_as_ushort(h0);
        uint32_t pl = ((uint32_t)__bfloat16_as_ushort(l1)<<16) | (uint32_t)__bfloat16_as_ushort(l0);
        sH[d*66 + sp] = ph;
        sL[d*66 + sp] = pl;
    }
    __syncthreads();
    #pragma unroll
    for (int i=0;i<16;i++){
        int flat = i*256 + t;
        int d = flat>>5, c2 = flat&31;
        uint2 vh = *(uint2*)&sH[d*66 + c2*2];
        uint2 vl = *(uint2*)&sL[d*66 + c2*2];
        size_t o32 = ((size_t)(bh*128+d)*2048 + sc0)/2 + c2*2;
        *(uint2*)((uint32_t*)dH + o32) = vh;
        *(uint2*)((uint32_t*)dL + o32) = vl;
    }
}

// ================= HMMA GEMM: cp.async pipeline, 2 CTAs/SM, barrier-hidden refill =================
#define TSTRIDE 40
#define TILE_BF16 (128*TSTRIDE)
#define TILE_U4   (TILE_BF16/8)
#define BUF_BYTES (4*TILE_BF16*2)
#define GEMM_SMEM (2*BUF_BYTES)

__global__ __launch_bounds__(256,2) void gemm_mma_kernel(
    const float* __restrict__ bq, const float* __restrict__ bk, const float* __restrict__ bv,
    float* __restrict__ outp, int asel)
{
    extern __shared__ char sm[];
    uint32_t sbase = smem_u32(sm);

    int t = threadIdx.x;
    int wid = t>>5, lane = t&31;
    int wm = wid>>2, wn = wid&3;
    int n0 = blockIdx.x*128;
    int m0 = blockIdx.y*128;
    int which = (asel==0) ? blockIdx.z : 3;
    const __nv_bfloat16* Ah = (asel==0) ? g_AH : g_CH;
    const __nv_bfloat16* Al = (asel==0) ? g_AL : g_CL;
    const __nv_bfloat16* Bh = g_WtH + (size_t)which*HIDN*HIDN;
    const __nv_bfloat16* Bl = g_WtL + (size_t)which*HIDN*HIDN;

    const __nv_bfloat16* gsrc[4] = {
        Ah + (size_t)m0*HIDN, Al + (size_t)m0*HIDN,
        Bh + (size_t)n0*HIDN, Bl + (size_t)n0*HIDN };

    const __nv_bfloat16* gp[8];
    uint32_t soff[8];
    #pragma unroll
    for (int i=0;i<8;i++){
        int slot = t + i*256;
        int tt = slot>>9;
        int w = slot&511;
        int rr = w>>2, cc = w&3;
        gp[i] = gsrc[tt] + (size_t)rr*HIDN + cc*8;
        soff[i] = (uint32_t)(tt*TILE_U4 + rr*5 + cc)*16u;
    }

    float acc[4][4][4];
    #pragma unroll
    for (int mt=0;mt<4;mt++)
        #pragma unroll
        for (int nt=0;nt<4;nt++)
            #pragma unroll
            for (int e=0;e<4;e++) acc[mt][nt][e] = 0.f;

    uint32_t aRow = (uint32_t)(wm*64 + (lane&15));
    uint32_t aChk = (uint32_t)(lane>>4);
    uint32_t bRow = (uint32_t)(wn*32 + (lane&7));
    uint32_t bChk = (uint32_t)((lane>>3)&1);

    #pragma unroll
    for (int i=0;i<8;i++) cp_async16(sbase + soff[i], gp[i]);
    CP_COMMIT();
    #pragma unroll
    for (int i=0;i<8;i++) cp_async16(sbase + BUF_BYTES + soff[i], gp[i] + 32);
    CP_COMMIT();

    for (int kt=0; kt<64; kt++){
        int cur = kt & 1;
        if (kt == 63) { CP_WAIT0(); } else { CP_WAIT1(); }
        __syncthreads();

        uint32_t bufb = sbase + (uint32_t)cur*BUF_BYTES;

        // ---- k16=0: load + mma
        {
            uint32_t aH[4][4], aL[4][4], bH[4][2], bL[4][2];
            #pragma unroll
            for (int mt=0;mt<4;mt++){
                uint32_t off = (aRow + mt*16)*80u + aChk*16u;
                ldsm_x4(aH[mt][0],aH[mt][1],aH[mt][2],aH[mt][3], bufb + 0*TILE_BF16*2 + off);
                ldsm_x4(aL[mt][0],aL[mt][1],aL[mt][2],aL[mt][3], bufb + 1*TILE_BF16*2 + off);
            }
            #pragma unroll
            for (int nt=0;nt<4;nt++){
                uint32_t off = (bRow + nt*8)*80u + bChk*16u;
                ldsm_x2(bH[nt][0],bH[nt][1], bufb + 2*TILE_BF16*2 + off);
                ldsm_x2(bL[nt][0],bL[nt][1], bufb + 3*TILE_BF16*2 + off);
            }
            #pragma unroll
            for (int mt=0;mt<4;mt++)
                #pragma unroll
                for (int nt=0;nt<4;nt++){
                    mma_bf16(acc[mt][nt], aH[mt], bH[nt]);
                    mma_bf16(acc[mt][nt], aH[mt], bL[nt]);
                    mma_bf16(acc[mt][nt], aL[mt], bH[nt]);
                }
        }

        // ---- k16=1: load fragments (reads complete before the barrier below)
        uint32_t aH1[4][4], aL1[4][4], bH1[4][2], bL1[4][2];
        #pragma unroll
        for (int mt=0;mt<4;mt++){
            uint32_t off = (aRow + mt*16)*80u + (2u + aChk)*16u;
            ldsm_x4(aH1[mt][0],aH1[mt][1],aH1[mt][2],aH1[mt][3], bufb + 0*TILE_BF16*2 + off);
            ldsm_x4(aL1[mt][0],aL1[mt][1],aL1[mt][2],aL1[mt][3], bufb + 1*TILE_BF16*2 + off);
        }
        #pragma unroll
        for (int nt=0;nt<4;nt++){
            uint32_t off = (bRow + nt*8)*80u + (2u + bChk)*16u;
            ldsm_x2(bH1[nt][0],bH1[nt][1], bufb + 2*TILE_BF16*2 + off);
            ldsm_x2(bL1[nt][0],bL1[nt][1], bufb + 3*TILE_BF16*2 + off);
        }

        // refill this buffer with chunk kt+2; barrier+issue hidden behind k16=1 MMAs below
        if (kt < 62){
            __syncthreads();
            int k0 = (kt+2)*32;
            #pragma unroll
            for (int i=0;i<8;i++) cp_async16(bufb - sbase + sbase + soff[i], gp[i] + k0);
            CP_COMMIT();
        }

        // ---- k16=1: mma (register-resident)
        #pragma unroll
        for (int mt=0;mt<4;mt++)
            #pragma unroll
            for (int nt=0;nt<4;nt++){
                mma_bf16(acc[mt][nt], aH1[mt], bH1[nt]);
                mma_bf16(acc[mt][nt], aH1[mt], bL1[nt]);
                mma_bf16(acc[mt][nt], aL1[mt], bH1[nt]);
            }
    }

    int rB = wm*64 + (lane>>2);
    int cB = wn*32 + (lane&3)*2;
    if (asel == 0){
        const float* bias = (which==0)?bq:((which==1)?bk:bv);
        int h = n0>>7;
        #pragma unroll
        for (int mt=0;mt<4;mt++){
            #pragma unroll
            for (int nt=0;nt<4;nt++){
                int row = rB + mt*16;
                int col = cB + nt*8;
                int n = n0 + col;
                #pragma unroll
                for (int half=0; half<2; half++){
                    int m = m0 + row + half*8;
                    int b = m>>11, s = m&2047;
                    size_t o = (((size_t)(b*HH+h))*SS + s)*DD + col;
                    float v0 = acc[mt][nt][half*2+0] + bias[n];
                    float v1 = acc[mt][nt][half*2+1] + bias[n+1];
                    if (which == 2){
                        g_v[o] = v0; g_v[o+1] = v1;
                    } else {
                        float* O = (which==0)?g_sq:g_sk;
                        O[o] = v0; O[o+1] = v1;
                    }
                }
            }
        }
    } else {
        #pragma unroll
        for (int mt=0;mt<4;mt++){
            #pragma unroll
            for (int nt=0;nt<4;nt++){
                int row = rB + mt*16;
                int col = cB + nt*8;
                #pragma unroll
                for (int half=0; half<2; half++){
                    size_t o = (size_t)(m0 + row + half*8)*HIDN + n0 + col;
                    outp[o]   = acc[mt][nt][half*2+0];
                    outp[o+1] = acc[mt][nt][half*2+1];
                }
            }
        }
    }
}

// ---------------- RoPE + sigma ----------------
__global__ __launch_bounds__(256) void rope_kernel(const int* __restrict__ pos)
{
    int t = threadIdx.x;
    long rid = (long)blockIdx.x*2 + (t>>7);
    int d = t & 127;
    int s  = (int)(rid & (SS-1));
    int bh = (int)(rid >> 11);
    int b  = bh >> 4;
    size_t base = (size_t)rid * DD;
    float qv = g_sq[base+d], kv = g_sk[base+d];
    float qo = (d<64)? -g_sq[base+d+64] : g_sq[base+d-64];
    float ko = (d<64)? -g_sk[base+d+64] : g_sk[base+d-64];
    int p = pos[(size_t)b*SS + s];
    float inv = expf(-0.14391156831212787f * (float)(d & 63));
    float ang = (float)p * inv;
    float sn, cs;
    sincosf(ang, &sn, &cs);
    float qn = qv*cs + qo*sn;
    float kn = kv*cs + ko*sn;
    float sq = (qn>0.f) ? qn+1.f : expf(qn);
    float sk = (kn>0.f) ? kn+1.f : expf(kn);
    __syncthreads();
    g_sq[base+d] = sq;
    g_sk[base+d] = sk;
    __nv_bfloat16 h,l;
    bf16split(qn,h,l); g_qH[base+d]=h;  g_qL[base+d]=l;
    bf16split(kn,h,l); g_kH[base+d]=h;  g_kL[base+d]=l;
    bf16split(sq,h,l); g_sqH[base+d]=h; g_sqL[base+d]=l;
}

// ---------------- den[row] = dot(sig_q[row], z[h]) ----------------
__global__ __launch_bounds__(256) void den_kernel(const float* __restrict__ z)
{
    int wid = threadIdx.x>>5, lane = threadIdx.x&31;
    int row = blockIdx.x*8 + wid;
    int h = (row>>11)&15;
    const float4* sq = (const float4*)(g_sq + (size_t)row*DD);
    const float4* zz = (const float4*)(z + h*DD);
    float4 a = sq[lane], b = zz[lane];
    float dot = a.x*b.x + a.y*b.y + a.z*b.z + a.w*b.w;
    #pragma unroll
    for (int o=16;o>0;o>>=1) dot += __shfl_down_sync(0xffffffffu, dot, o);
    if (lane==0) g_den[row] = dot;
}

// ---------------- memory retrieval via HMMA ----------------
#define MR_TILE (128*136*2)
__global__ __launch_bounds__(256) void memret_mma_kernel()
{
    extern __shared__ char sm[];
    uint32_t sb = smem_u32(sm);
    float* denS = (float*)(sm + 4*MR_TILE);
    int s0 = blockIdx.x * 128;
    int bh = blockIdx.y;
    int h  = bh & 15;
    int t = threadIdx.x, wid=t>>5, lane=t&31;
    int wm = wid>>2, wn = wid&3;
    size_t rowbase = (size_t)bh*SS + s0;

    const uint4* srcs[4] = {
        (const uint4*)g_sqH + rowbase*16, (const uint4*)g_sqL + rowbase*16,
        (const uint4*)g_MtH + (size_t)h*2048, (const uint4*)g_MtL + (size_t)h*2048 };
    uint4* s4 = (uint4*)sm;
    #pragma unroll
    for (int i=0;i<32;i++){
        int slot = t + i*256;
        int sp = slot>>11, r = (slot>>4)&127, c16 = slot&15;
        s4[sp*(MR_TILE/16) + r*17 + c16] = srcs[sp][(size_t)r*16 + c16];
    }
    if (t < 128) denS[t] = g_den[rowbase + t];
    __syncthreads();

    float acc[4][4][4];
    #pragma unroll
    for (int mt=0;mt<4;mt++)
        #pragma unroll
        for (int nt=0;nt<4;nt++)
            #pragma unroll
            for (int e=0;e<4;e++) acc[mt][nt][e]=0.f;

    uint32_t aRow = (uint32_t)(wm*64 + (lane&15));
    uint32_t aChk = (uint32_t)(lane>>4);
    uint32_t bRow = (uint32_t)(wn*32 + (lane&7));
    uint32_t bChk = (uint32_t)((lane>>3)&1);

    #pragma unroll
    for (int kf=0; kf<8; kf++){
        uint32_t aH[4][4], aL[4][4], bH[4][2], bL[4][2];
        #pragma unroll
        for (int mt=0;mt<4;mt++){
            uint32_t off = (aRow + mt*16)*272u + (kf*2 + aChk)*16u;
            ldsm_x4(aH[mt][0],aH[mt][1],aH[mt][2],aH[mt][3], sb + 0*MR_TILE + off);
            ldsm_x4(aL[mt][0],aL[mt][1],aL[mt][2],aL[mt][3], sb + 1*MR_TILE + off);
        }
        #pragma unroll
        for (int nt=0;nt<4;nt++){
            uint32_t off = (bRow + nt*8)*272u + (kf*2 + bChk)*16u;
            ldsm_x2(bH[nt][0],bH[nt][1], sb + 2*MR_TILE + off);
            ldsm_x2(bL[nt][0],bL[nt][1], sb + 3*MR_TILE + off);
        }
        #pragma unroll
        for (int mt=0;mt<4;mt++)
            #pragma unroll
            for (int nt=0;nt<4;nt++){
                mma_bf16(acc[mt][nt], aH[mt], bH[nt]);
                mma_bf16(acc[mt][nt], aH[mt], bL[nt]);
                mma_bf16(acc[mt][nt], aL[mt], bH[nt]);
            }
    }

    int rB = wm*64 + (lane>>2);
    int cB = wn*32 + (lane&3)*2;
    size_t obase = ((size_t)bh*SS + s0)*DD;
    #pragma unroll
    for (int mt=0;mt<4;mt++)
        #pragma unroll
        for (int nt=0;nt<4;nt++)
            #pragma unroll
            for (int half=0; half<2; half++){
                int row = rB + mt*16 + half*8;
                int col = cB + nt*8;
                float dinv = 1.f/denS[row];
                g_mem[obase + (size_t)row*DD + col]   = acc[mt][nt][half*2+0]*dinv;
                g_mem[obase + (size_t)row*DD + col+1] = acc[mt][nt][half*2+1]*dinv;
            }
}

// ---------------- flash attention via HMMA, split precision ----------------
#define FQ_H 0
#define FQ_L 34816
#define FK_H 69632
#define FK_L 87040
#define FVT_H 104448
#define FVT_L 122880
#define FPS 141312
#define FP_H 174592
#define FP_L 193024
#define FMR 211456
#define FSCR 212992
#define FTOT 215040

__global__ __launch_bounds__(256,1) void attn_mma_kernel()
{
    extern __shared__ char sm[];
    uint32_t sb = smem_u32(sm);
    float* PS   = (float*)(sm + FPS);
    __nv_bfloat16* PH  = (__nv_bfloat16*)(sm + FP_H);
    __nv_bfloat16* PL  = (__nv_bfloat16*)(sm + FP_L);
    float* mrow = (float*)(sm + FMR);
    float* lrow = mrow + 128;
    float* rs   = lrow + 128;
    float* scrA = (float*)(sm + FSCR);
    float* scrB = scrA + 256;

    int qb = 15 - blockIdx.x;
    int bh = blockIdx.y;
    int t = threadIdx.x, wid=t>>5, lane=t&31;
    int wm = wid>>2, wn = wid&3;
    size_t rowbase = (size_t)bh*SS;
    size_t base = rowbase*DD;

    {
        uint4* s4 = (uint4*)sm;
        const uint4* q4[2] = { (const uint4*)g_qH + (rowbase + qb*128)*16,
                               (const uint4*)g_qL + (rowbase + qb*128)*16 };
        #pragma unroll
        for (int i=0;i<16;i++){
            int slot = t + i*256;
            int sp = slot>>11, r = (slot>>4)&127, c16 = slot&15;
            s4[(sp*34816)/16 + r*17 + c16] = q4[sp][(size_t)r*16 + c16];
        }
    }
    if (t < 128){ mrow[t] = -INFINITY; lrow[t] = 0.f; }

    float oacc[4][4][4];
    #pragma unroll
    for (int mt=0;mt<4;mt++)
        #pragma unroll
        for (int nt=0;nt<4;nt++)
            #pragma unroll
            for (int e=0;e<4;e++) oacc[mt][nt][e]=0.f;
    __syncthreads();

    const float sscale = 0.08838834764831845f;
    uint32_t aRow = (uint32_t)(wm*64 + (lane&15));
    uint32_t aChk = (uint32_t)(lane>>4);
    uint32_t bRowS = (uint32_t)(wn*16 + (lane&7));
    uint32_t bRowV = (uint32_t)(wn*32 + (lane&7));
    uint32_t bChk = (uint32_t)((lane>>3)&1);
    int rB = wm*64 + (lane>>2);
    int srow = t>>1, shalf = t&1;

    int jbmax = 2*qb + 1;
    for (int jb=0; jb<=jbmax; jb++){
        {
            uint4* s4 = (uint4*)(sm + FK_H);
            const uint4* k4[2] = { (const uint4*)g_kH + (rowbase + jb*64)*16,
                                   (const uint4*)g_kL + (rowbase + jb*64)*16 };
            #pragma unroll
            for (int i=0;i<8;i++){
                int slot = t + i*256;
                int sp = slot>>10, r = (slot>>4)&63, c16 = slot&15;
                s4[(sp*17408)/16 + r*17 + c16] = k4[sp][(size_t)r*16 + c16];
            }
        }
        #pragma unroll
        for (int i=0;i<8;i++){
            int slot = t + i*256;
            int sp = slot>>10, r = (slot>>3)&127, c = slot&7;
            const __nv_bfloat16* src = sp ? g_vTL : g_vTH;
            uint4 v = *(const uint4*)(src + (size_t)(bh*128+r)*2048 + jb*64 + c*8);
            *(uint4*)(sm + FVT_H + sp*18432 + r*144 + c*16) = v;
        }
        __syncthreads();

        float sacc[4][2][4];
        #pragma unroll
        for (int mt=0;mt<4;mt++)
            #pragma unroll
            for (int nt=0;nt<2;nt++)
                #pragma unroll
                for (int e=0;e<4;e++) sacc[mt][nt][e]=0.f;
        #pragma unroll
        for (int kf=0; kf<8; kf++){
            uint32_t aH[4][4], aL[4][4], bH[2][2], bL[2][2];
            #pragma unroll
            for (int mt=0;mt<4;mt++){
                uint32_t off = (aRow + mt*16)*272u + (kf*2 + aChk)*16u;
                ldsm_x4(aH[mt][0],aH[mt][1],aH[mt][2],aH[mt][3], sb + FQ_H + off);
                ldsm_x4(aL[mt][0],aL[mt][1],aL[mt][2],aL[mt][3], sb + FQ_L + off);
            }
            #pragma unroll
            for (int nt=0;nt<2;nt++){
                uint32_t off = (bRowS + nt*8)*272u + (kf*2 + bChk)*16u;
                ldsm_x2(bH[nt][0],bH[nt][1], sb + FK_H + off);
                ldsm_x2(bL[nt][0],bL[nt][1], sb + FK_L + off);
            }
            #pragma unroll
            for (int mt=0;mt<4;mt++)
                #pragma unroll
                for (int nt=0;nt<2;nt++){
                    mma_bf16(sacc[mt][nt], aH[mt], bH[nt]);
                    mma_bf16(sacc[mt][nt], aH[mt], bL[nt]);
                    mma_bf16(sacc[mt][nt], aL[mt], bH[nt]);
                }
        }
        {
            int cBs = wn*16 + (lane&3)*2;
            #pragma unroll
            for (int mt=0;mt<4;mt++)
                #pragma unroll
                for (int nt=0;nt<2;nt++)
                    #pragma unroll
                    for (int half=0; half<2; half++){
                        int row = rB + mt*16 + half*8;
                        int col = cBs + nt*8;
                        int qrow = qb*128 + row, kcol = jb*64 + col;
                        PS[row*65+col]   = (kcol   <= qrow) ? sacc[mt][nt][half*2+0]*sscale : -INFINITY;
                        PS[row*65+col+1] = (kcol+1 <= qrow) ? sacc[mt][nt][half*2+1]*sscale : -INFINITY;
                    }
        }
        __syncthreads();

        {
            float* PSrow = PS + srow*65 + shalf*32;
            float pm = -INFINITY;
            #pragma unroll 8
            for (int j=0;j<32;j++) pm = fmaxf(pm, PSrow[j]);
            scrA[t] = pm;
            __syncthreads();
            float m_new = fmaxf(mrow[srow], fmaxf(scrA[2*srow], scrA[2*srow+1]));
            float psum = 0.f;
            #pragma unroll 8
            for (int j=0;j<32;j++){
                float p = __expf(PSrow[j] - m_new);
                PSrow[j] = p;
                psum += p;
            }
            scrB[t] = psum;
            __syncthreads();
            if (t < 128){
                float mo = mrow[t];
                float mn = fmaxf(mo, fmaxf(scrA[2*t], scrA[2*t+1]));
                float sc = __expf(mo - mn);
                lrow[t] = sc*lrow[t] + scrB[2*t] + scrB[2*t+1];
                mrow[t] = mn;
                rs[t]   = sc;
            }
        }
        __syncthreads();

        #pragma unroll
        for (int i=0;i<32;i++){
            int e = i*256 + t;
            int row = e>>6, col = e&63;
            __nv_bfloat16 h,l; bf16split(PS[row*65+col], h, l);
            PH[row*72+col] = h; PL[row*72+col] = l;
        }
        __syncthreads();

        #pragma unroll
        for (int mt=0;mt<4;mt++){
            float s0 = rs[rB + mt*16], s1 = rs[rB + mt*16 + 8];
            #pragma unroll
            for (int nt=0;nt<4;nt++){
                oacc[mt][nt][0] *= s0; oacc[mt][nt][1] *= s0;
                oacc[mt][nt][2] *= s1; oacc[mt][nt][3] *= s1;
            }
        }
        #pragma unroll
        for (int kf=0; kf<4; kf++){
            uint32_t aH[4][4], aL[4][4], bH[4][2], bL[4][2];
            #pragma unroll
            for (int mt=0;mt<4;mt++){
                uint32_t off = (aRow + mt*16)*144u + (kf*2 + aChk)*16u;
                ldsm_x4(aH[mt][0],aH[mt][1],aH[mt][2],aH[mt][3], sb + FP_H + off);
                ldsm_x4(aL[mt][0],aL[mt][1],aL[mt][2],aL[mt][3], sb + FP_L + off);
            }
            #pragma unroll
            for (int nt=0;nt<4;nt++){
                uint32_t off = (bRowV + nt*8)*144u + (kf*2 + bChk)*16u;
                ldsm_x2(bH[nt][0],bH[nt][1], sb + FVT_H + off);
                ldsm_x2(bL[nt][0],bL[nt][1], sb + FVT_L + off);
            }
            #pragma unroll
            for (int mt=0;mt<4;mt++)
                #pragma unroll
                for (int nt=0;nt<4;nt++){
                    mma_bf16(oacc[mt][nt], aH[mt], bH[nt]);
                    mma_bf16(oacc[mt][nt], aH[mt], bL[nt]);
                    mma_bf16(oacc[mt][nt], aL[mt], bH[nt]);
                }
        }
        __syncthreads();
    }

    int cB = wn*32 + (lane&3)*2;
    #pragma unroll
    for (int mt=0;mt<4;mt++)
        #pragma unroll
        for (int half=0; half<2; half++){
            int row = rB + mt*16 + half*8;
            float linv = 1.f/lrow[row];
            #pragma unroll
            for (int nt=0;nt<4;nt++){
                int col = cB + nt*8;
                size_t o = base + (size_t)(qb*128+row)*DD + col;
                g_att[o]   = oacc[mt][nt][half*2+0]*linv;
                g_att[o+1] = oacc[mt][nt][half*2+1]*linv;
            }
        }
}

// ---------------- M update via HMMA from pre-transposed skT/vT ----------------
__global__ __launch_bounds__(256) void m_update_mma_kernel()
{
    __shared__ __nv_bfloat16 tiles[4*TILE_BF16];   // 40KB: skTH, skTL, vTH, vTL
    uint32_t sb = smem_u32(tiles);

    int h = blockIdx.x, c = blockIdx.y;
    int b = c>>3, s0 = (c&7)*256;
    int bh = b*HH + h;
    int t = threadIdx.x, wid=t>>5, lane=t&31;
    int wm = wid>>2, wn = wid&3;

    const uint4* gsrc[4] = {
        (const uint4*)g_skTH + (size_t)bh*128*256,
        (const uint4*)g_skTL + (size_t)bh*128*256,
        (const uint4*)g_vTH  + (size_t)bh*128*256,
        (const uint4*)g_vTL  + (size_t)bh*128*256 };

    int sp[8], rr[8], cc[8];
    #pragma unroll
    for (int i=0;i<8;i++){
        int slot = t + i*256;
        sp[i] = slot>>9;
        int w = slot&511;
        rr[i] = w>>2;
        cc[i] = w&3;
    }

    float acc[4][4][4];
    #pragma unroll
    for (int mt=0;mt<4;mt++)
        #pragma unroll
        for (int nt=0;nt<4;nt++)
            #pragma unroll
            for (int e=0;e<4;e++) acc[mt][nt][e]=0.f;
    float zacc = 0.f;

    uint32_t aRow = (uint32_t)(wm*64 + (lane&15));
    uint32_t aChk = (uint32_t)(lane>>4);
    uint32_t bRow = (uint32_t)(wn*32 + (lane&7));
    uint32_t bChk = (uint32_t)((lane>>3)&1);

    for (int kc=0; kc<8; kc++){
        int cu = (s0 + kc*32)>>3;   // uint4 col offset
        uint4* s4 = (uint4*)tiles;
        #pragma unroll
        for (int i=0;i<8;i++)
            s4[sp[i]*TILE_U4 + rr[i]*5 + cc[i]] = gsrc[sp[i]][(size_t)rr[i]*256 + cu + cc[i]];
        __syncthreads();

        if (t < 128){
            const __nv_bfloat16* rowH = tiles + 0*TILE_BF16 + t*TSTRIDE;
            const __nv_bfloat16* rowL = tiles + 1*TILE_BF16 + t*TSTRIDE;
            #pragma unroll
            for (int s=0;s<32;s++)
                zacc += __bfloat162float(rowH[s]) + __bfloat162float(rowL[s]);
        }

        #pragma unroll
        for (int kf=0; kf<2; kf++){
            uint32_t aH[4][4], aL[4][4], bH[4][2], bL[4][2];
            #pragma unroll
            for (int mt=0;mt<4;mt++){
                uint32_t off = (aRow + mt*16)*80u + (kf*2 + aChk)*16u;
                ldsm_x4(aH[mt][0],aH[mt][1],aH[mt][2],aH[mt][3], sb + 0*TILE_BF16*2 + off);
                ldsm_x4(aL[mt][0],aL[mt][1],aL[mt][2],aL[mt][3], sb + 1*TILE_BF16*2 + off);
            }
            #pragma unroll
            for (int nt=0;nt<4;nt++){
                uint32_t off = (bRow + nt*8)*80u + (kf*2 + bChk)*16u;
                ldsm_x2(bH[nt][0],bH[nt][1], sb + 2*TILE_BF16*2 + off);
                ldsm_x2(bL[nt][0],bL[nt][1], sb + 3*TILE_BF16*2 + off);
            }
            #pragma unroll
            for (int mt=0;mt<4;mt++)
                #pragma unroll
                for (int nt=0;nt<4;nt++){
                    mma_bf16(acc[mt][nt], aH[mt], bH[nt]);
                    mma_bf16(acc[mt][nt], aH[mt], bL[nt]);
                    mma_bf16(acc[mt][nt], aL[mt], bH[nt]);
                }
        }
        __syncthreads();
    }

    if (t < 128) g_zpart[(h*16 + c)*DD + t] = zacc;

    size_t pbase = ((size_t)(h*16 + c)) << 14;
    int rB = wm*64 + (lane>>2);
    int cB = wn*32 + (lane&3)*2;
    #pragma unroll
    for (int mt=0;mt<4;mt++)
        #pragma unroll
        for (int nt=0;nt<4;nt++)
            #pragma unroll
            for (int half=0; half<2; half++){
                int row = rB + mt*16 + half*8;   // d
                int col = cB + nt*8;              // e
                g_mpart[pbase + (size_t)row*DD + col]   = acc[mt][nt][half*2+0];
                g_mpart[pbase + (size_t)row*DD + col+1] = acc[mt][nt][half*2+1];
            }
}

__global__ void reduce_m_kernel(const float* __restrict__ M, float* __restrict__ out)
{
    int idx = blockIdx.x*256 + threadIdx.x;
    int h = idx >> 14;
    int de = idx & 16383;
    float s = M[idx];
    #pragma unroll
    for (int c=0;c<16;c++) s += g_mpart[(((size_t)(h*16+c))<<14) + de];
    out[idx] = s;
}

__global__ void reduce_z_kernel(const float* __restrict__ z, float* __restrict__ out)
{
    int idx = blockIdx.x*256 + threadIdx.x;
    float s = z[idx];
    int h = idx >> 7, d = idx & 127;
    #pragma unroll
    for (int c=0;c<16;c++) s += g_zpart[(h*16+c)*DD + d];
    out[idx] = s;
}

// ---------------- launch ----------------
extern "C" void kernel_launch(void* const* d_in, const int* in_sizes, int n_in,
                              void* d_out, int out_size)
{
    (void)in_sizes; (void)n_in; (void)out_size;
    const float* hs   = (const float*)d_in[0];
    const float* Wq   = (const float*)d_in[1];
    const float* bq   = (const float*)d_in[2];
    const float* Wk   = (const float*)d_in[3];
    const float* bk   = (const float*)d_in[4];
    const float* Wv   = (const float*)d_in[5];
    const float* bv   = (const float*)d_in[6];
    const float* Wo   = (const float*)d_in[7];
    const float* beta = (const float*)d_in[8];
    const float* Mm   = (const float*)d_in[9];
    const float* zz   = (const float*)d_in[10];
    const int* pos    = (const int*)d_in[12];
    float* out = (float*)d_out;

    cudaFuncSetAttribute(attn_mma_kernel, cudaFuncAttributeMaxDynamicSharedMemorySize, FTOT);
    cudaFuncSetAttribute(memret_mma_kernel, cudaFuncAttributeMaxDynamicSharedMemorySize, 4*MR_TILE + 512);
    cudaFuncSetAttribute(gemm_mma_kernel, cudaFuncAttributeMaxDynamicSharedMemorySize, GEMM_SMEM);
    cudaFuncSetAttribute(tsplit_kernel, cudaFuncAttributeMaxDynamicSharedMemorySize, VT_SMEM);

    split_a_kernel<<<MTOT*HIDN/256, 256>>>(hs);
    wsplit_kernel<<<dim3(64,64,4), 256>>>(Wq, Wk, Wv, Wo);
    msplit_kernel<<<1024, 256>>>(Mm);

    // QKV (q->g_sq staging, k->g_sk staging, v->g_v)
    gemm_mma_kernel<<<dim3(16,32,3), 256, GEMM_SMEM>>>(bq, bk, bv, nullptr, 0);

    rope_kernel<<<BHS/2, 256>>>(pos);

    // transpose+split V (z=0) and sigma(k) (z=1)
    tsplit_kernel<<<dim3(32,16,2), 256, VT_SMEM>>>();

    den_kernel<<<BHS/8, 256>>>(zz);
    memret_mma_kernel<<<dim3(16,32), 256, 4*MR_TILE + 512>>>();

    attn_mma_kernel<<<dim3(16,32), 256, FTOT>>>();

    m_update_mma_kernel<<<dim3(16,16), 256>>>();
    reduce_m_kernel<<<1024, 256>>>(Mm, out + 8388608);
    reduce_z_kernel<<<8, 256>>>(zz, out + 8388608 + 262144);

    combine_split_kernel<<<MTOT*HIDN/256, 256>>>(beta);
    gemm_mma_kernel<<<dim3(16,32,1), 256, GEMM_SMEM>>>(bq, bk, bv, out, 1);
}

// round 15
// speedup vs baseline: 1.4673x; 1.4673x over previous
#include <cuda_runtime.h>
#include <cuda_bf16.h>
#include <math.h>
#include <stdint.h>

#define BB 2
#define SS 2048
#define HH 16
#define DD 128
#define HIDN 2048
#define BHS (BB*HH*SS)
#define MTOT 4096

// ---------------- scratch ----------------
__device__ float g_v  [BB*HH*SS*DD];
__device__ float g_sq [BB*HH*SS*DD];
__device__ float g_sk [BB*HH*SS*DD];
__device__ float g_mem[BB*HH*SS*DD];
__device__ float g_att[BB*HH*SS*DD];
__device__ float g_den[BHS];
__device__ float g_mpart[HH*16*DD*DD];
__device__ float g_zpart[HH*16*DD];

__device__ __nv_bfloat16 g_AH[MTOT*HIDN];
__device__ __nv_bfloat16 g_AL[MTOT*HIDN];
__device__ __nv_bfloat16 g_WtH[4u*HIDN*HIDN];
__device__ __nv_bfloat16 g_WtL[4u*HIDN*HIDN];
__device__ __nv_bfloat16 g_CH[MTOT*HIDN];
__device__ __nv_bfloat16 g_CL[MTOT*HIDN];
__device__ __nv_bfloat16 g_qH[BB*HH*SS*DD];
__device__ __nv_bfloat16 g_qL[BB*HH*SS*DD];
__device__ __nv_bfloat16 g_kH[BB*HH*SS*DD];
__device__ __nv_bfloat16 g_kL[BB*HH*SS*DD];
__device__ __nv_bfloat16 g_sqH[BB*HH*SS*DD];
__device__ __nv_bfloat16 g_sqL[BB*HH*SS*DD];
__device__ __nv_bfloat16 g_MtH[HH*DD*DD];
__device__ __nv_bfloat16 g_MtL[HH*DD*DD];
__device__ __nv_bfloat16 g_vTH[BB*HH*SS*DD];   // V^T [bh][d][s] splits
__device__ __nv_bfloat16 g_vTL[BB*HH*SS*DD];

// ================= mma.sync helpers =================
__device__ __forceinline__ uint32_t smem_u32(const void* p){
    return (uint32_t)__cvta_generic_to_shared(p);
}
__device__ __forceinline__ void ldsm_x4(uint32_t& r0, uint32_t& r1, uint32_t& r2, uint32_t& r3, uint32_t addr){
    asm volatile("ldmatrix.sync.aligned.m8n8.x4.shared.b16 {%0,%1,%2,%3}, [%4];"
        : "=r"(r0), "=r"(r1), "=r"(r2), "=r"(r3) : "r"(addr));
}
__device__ __forceinline__ void ldsm_x2(uint32_t& r0, uint32_t& r1, uint32_t addr){
    asm volatile("ldmatrix.sync.aligned.m8n8.x2.shared.b16 {%0,%1}, [%2];"
        : "=r"(r0), "=r"(r1) : "r"(addr));
}
__device__ __forceinline__ void mma_bf16(float* d, const uint32_t* a, const uint32_t* b){
    asm volatile("mma.sync.aligned.m16n8k16.row.col.f32.bf16.bf16.f32 "
        "{%0,%1,%2,%3}, {%4,%5,%6,%7}, {%8,%9}, {%0,%1,%2,%3};"
        : "+f"(d[0]), "+f"(d[1]), "+f"(d[2]), "+f"(d[3])
        : "r"(a[0]), "r"(a[1]), "r"(a[2]), "r"(a[3]), "r"(b[0]), "r"(b[1]));
}
__device__ __forceinline__ void bf16split(float v, __nv_bfloat16& h, __nv_bfloat16& l){
    h = __float2bfloat16_rn(v);
    l = __float2bfloat16_rn(v - __bfloat162float(h));
}
__device__ __forceinline__ void cp_async16(uint32_t smem_addr, const void* gptr){
    asm volatile("cp.async.cg.shared.global [%0], [%1], 16;" :: "r"(smem_addr), "l"(gptr));
}
#define CP_COMMIT() asm volatile("cp.async.commit_group;" ::: "memory")
#define CP_WAIT2()  asm volatile("cp.async.wait_group 2;" ::: "memory")
#define CP_WAIT1()  asm volatile("cp.async.wait_group 1;" ::: "memory")
#define CP_WAIT0()  asm volatile("cp.async.wait_group 0;" ::: "memory")

// ================= pre-pass kernels =================
__global__ __launch_bounds__(256) void split_a_kernel(const float* __restrict__ A)
{
    int idx = blockIdx.x*256 + threadIdx.x;
    __nv_bfloat16 h,l; bf16split(A[idx], h, l);
    g_AH[idx] = h; g_AL[idx] = l;
}

__global__ __launch_bounds__(256) void wsplit_kernel(
    const float* __restrict__ Wq, const float* __restrict__ Wk,
    const float* __restrict__ Wv, const float* __restrict__ Wo)
{
    __shared__ float tile[32][33];
    int z = blockIdx.z;
    const float* W = (z==0)?Wq:((z==1)?Wk:((z==2)?Wv:Wo));
    __nv_bfloat16* H = g_WtH + (size_t)z*HIDN*HIDN;
    __nv_bfloat16* L = g_WtL + (size_t)z*HIDN*HIDN;
    int n0 = blockIdx.x*32, k0 = blockIdx.y*32;
    int tx = threadIdx.x & 31, ty = threadIdx.x >> 5;
    #pragma unroll
    for (int i=0;i<4;i++)
        tile[ty+8*i][tx] = W[(size_t)(k0+ty+8*i)*HIDN + n0+tx];
    __syncthreads();
    #pragma unroll
    for (int i=0;i<4;i++){
        __nv_bfloat16 h,l; bf16split(tile[tx][ty+8*i], h, l);
        size_t o = (size_t)(n0+ty+8*i)*HIDN + k0+tx;
        H[o] = h; L[o] = l;
    }
}

__global__ __launch_bounds__(256) void msplit_kernel(const float* __restrict__ M)
{
    int idx = blockIdx.x*256 + threadIdx.x;
    int h = idx >> 14, d = (idx>>7)&127, e = idx&127;
    __nv_bfloat16 hh,ll; bf16split(M[idx], hh, ll);
    size_t o = (size_t)h*16384 + e*128 + d;
    g_MtH[o] = hh; g_MtL[o] = ll;
}

__global__ __launch_bounds__(256) void combine_split_kernel(const float* __restrict__ beta)
{
    int idx = blockIdx.x*256 + threadIdx.x;
    float g = 1.f/(1.f + expf(-beta[0]));
    int m = idx >> 11, kcol = idx & 2047;
    int b = m>>11, s = m&2047, h = kcol>>7, d = kcol&127;
    size_t a = (((size_t)(b*HH+h))*SS + s)*DD + d;
    float v = g*g_mem[a] + (1.f-g)*g_att[a];
    __nv_bfloat16 hh,ll; bf16split(v, hh, ll);
    g_CH[idx] = hh; g_CL[idx] = ll;
}

// transpose+split V: [bh][s][d] fp32 -> [bh][d][s] bf16 H/L.
#define VT_SMEM (2*128*66*4)
__global__ __launch_bounds__(256) void vsplitT_kernel()
{
    extern __shared__ char sm[];
    uint32_t* sH = (uint32_t*)sm;            // [128 d][66]
    uint32_t* sL = sH + 128*66;
    int bh = blockIdx.x, sc0 = blockIdx.y*128;
    int t = threadIdx.x;
    size_t base = ((size_t)bh*SS + sc0)*DD;
    #pragma unroll
    for (int i=0;i<32;i++){
        int pidx = i*256 + t;
        int d = pidx & 127, sp = pidx >> 7;
        float v0 = g_v[base + (size_t)(2*sp)*DD + d];
        float v1 = g_v[base + (size_t)(2*sp+1)*DD + d];
        __nv_bfloat16 h0,l0,h1,l1;
        bf16split(v0,h0,l0); bf16split(v1,h1,l1);
        uint32_t ph = ((uint32_t)__bfloat16_as_ushort(h1)<<16) | (uint32_t)__bfloat16_as_ushort(h0);
        uint32_t pl = ((uint32_t)__bfloat16_as_ushort(l1)<<16) | (uint32_t)__bfloat16_as_ushort(l0);
        sH[d*66 + sp] = ph;
        sL[d*66 + sp] = pl;
    }
    __syncthreads();
    #pragma unroll
    for (int i=0;i<16;i++){
        int flat = i*256 + t;
        int d = flat>>5, c2 = flat&31;
        uint2 vh = *(uint2*)&sH[d*66 + c2*2];
        uint2 vl = *(uint2*)&sL[d*66 + c2*2];
        size_t o32 = ((size_t)(bh*128+d)*2048 + sc0)/2 + c2*2;
        *(uint2*)((uint32_t*)g_vTH + o32) = vh;
        *(uint2*)((uint32_t*)g_vTL + o32) = vl;
    }
}

// ================= HMMA GEMM: 4-stage cp.async pipeline (BK=16), 2 CTAs/SM =================
#define TS2 24                          // smem row stride in bf16 (48B; 48r mod 128 hits 8 distinct 16B offsets)
#define TILE2_BF16 (128*TS2)            // 3072 bf16 per tile
#define STAGE_BYTES (4*TILE2_BF16*2)    // 24576 B per stage (Ah, Al, Bh, Bl)
#define GEMM_SMEM (4*STAGE_BYTES)       // 98304 B

__global__ __launch_bounds__(256,2) void gemm_mma_kernel(
    const float* __restrict__ bq, const float* __restrict__ bk, const float* __restrict__ bv,
    float* __restrict__ outp, int asel)
{
    extern __shared__ char sm[];
    uint32_t sbase = smem_u32(sm);

    int t = threadIdx.x;
    int wid = t>>5, lane = t&31;
    int wm = wid>>2, wn = wid&3;
    int n0 = blockIdx.x*128;
    int m0 = blockIdx.y*128;
    int which = (asel==0) ? blockIdx.z : 3;
    const __nv_bfloat16* Ah = (asel==0) ? g_AH : g_CH;
    const __nv_bfloat16* Al = (asel==0) ? g_AL : g_CL;
    const __nv_bfloat16* Bh = g_WtH + (size_t)which*HIDN*HIDN;
    const __nv_bfloat16* Bl = g_WtL + (size_t)which*HIDN*HIDN;

    const __nv_bfloat16* gsrc[4] = {
        Ah + (size_t)m0*HIDN, Al + (size_t)m0*HIDN,
        Bh + (size_t)n0*HIDN, Bl + (size_t)n0*HIDN };

    // per-thread 4 load slots per stage: 1024 uint4 per stage total
    const __nv_bfloat16* gp[4];
    uint32_t soff[4];
    #pragma unroll
    for (int i=0;i<4;i++){
        int slot = t + i*256;
        int sp = slot>>8;          // tile 0..3
        int w = slot&255;
        int rr = w>>1, cc = w&1;   // row 0..127, 16B-chunk 0..1
        gp[i] = gsrc[sp] + (size_t)rr*HIDN + cc*8;
        soff[i] = (uint32_t)(sp*(TILE2_BF16*2) + rr*48 + cc*16);
    }

    float acc[4][4][4];
    #pragma unroll
    for (int mt=0;mt<4;mt++)
        #pragma unroll
        for (int nt=0;nt<4;nt++)
            #pragma unroll
            for (int e=0;e<4;e++) acc[mt][nt][e] = 0.f;

    uint32_t aRow = (uint32_t)(wm*64 + (lane&15));
    uint32_t aChk = (uint32_t)(lane>>4);
    uint32_t bRow = (uint32_t)(wn*32 + (lane&7));
    uint32_t bChk = (uint32_t)((lane>>3)&1);

    // prologue: chunks 0,1,2 in flight
    #pragma unroll
    for (int s=0;s<3;s++){
        #pragma unroll
        for (int i=0;i<4;i++) cp_async16(sbase + (uint32_t)s*STAGE_BYTES + soff[i], gp[i] + s*16);
        CP_COMMIT();
    }

    for (int it=0; it<128; it++){
        if (it < 126) { CP_WAIT2(); } else if (it == 126) { CP_WAIT1(); } else { CP_WAIT0(); }
        __syncthreads();

        // refill: chunk it+3 -> stage (it+3)&3 (its reads finished at iter it-1; sync above guards)
        if (it < 125){
            uint32_t rb = sbase + (uint32_t)((it+3)&3)*STAGE_BYTES;
            int k0 = (it+3)*16;
            #pragma unroll
            for (int i=0;i<4;i++) cp_async16(rb + soff[i], gp[i] + k0);
            CP_COMMIT();
        }

        // compute stage it&3 (one k16), JIT fragments
        uint32_t bufb = sbase + (uint32_t)(it&3)*STAGE_BYTES;
        uint32_t aH[4][4], aL[4][4], bH[4][2], bL[4][2];
        #pragma unroll
        for (int mt=0;mt<4;mt++){
            uint32_t off = (aRow + mt*16)*48u + aChk*16u;
            ldsm_x4(aH[mt][0],aH[mt][1],aH[mt][2],aH[mt][3], bufb + 0*TILE2_BF16*2 + off);
            ldsm_x4(aL[mt][0],aL[mt][1],aL[mt][2],aL[mt][3], bufb + 1*TILE2_BF16*2 + off);
        }
        #pragma unroll
        for (int nt=0;nt<4;nt++){
            uint32_t off = (bRow + nt*8)*48u + bChk*16u;
            ldsm_x2(bH[nt][0],bH[nt][1], bufb + 2*TILE2_BF16*2 + off);
            ldsm_x2(bL[nt][0],bL[nt][1], bufb + 3*TILE2_BF16*2 + off);
        }
        #pragma unroll
        for (int mt=0;mt<4;mt++)
            #pragma unroll
            for (int nt=0;nt<4;nt++){
                mma_bf16(acc[mt][nt], aH[mt], bH[nt]);
                mma_bf16(acc[mt][nt], aH[mt], bL[nt]);
                mma_bf16(acc[mt][nt], aL[mt], bH[nt]);
            }
    }

    int rB = wm*64 + (lane>>2);
    int cB = wn*32 + (lane&3)*2;
    if (asel == 0){
        const float* bias = (which==0)?bq:((which==1)?bk:bv);
        int h = n0>>7;
        #pragma unroll
        for (int mt=0;mt<4;mt++){
            #pragma unroll
            for (int nt=0;nt<4;nt++){
                int row = rB + mt*16;
                int col = cB + nt*8;
                int n = n0 + col;
                #pragma unroll
                for (int half=0; half<2; half++){
                    int m = m0 + row + half*8;
                    int b = m>>11, s = m&2047;
                    size_t o = (((size_t)(b*HH+h))*SS + s)*DD + col;
                    float v0 = acc[mt][nt][half*2+0] + bias[n];
                    float v1 = acc[mt][nt][half*2+1] + bias[n+1];
                    if (which == 2){
                        g_v[o] = v0; g_v[o+1] = v1;
                    } else {
                        float* O = (which==0)?g_sq:g_sk;
                        O[o] = v0; O[o+1] = v1;
                    }
                }
            }
        }
    } else {
        #pragma unroll
        for (int mt=0;mt<4;mt++){
            #pragma unroll
            for (int nt=0;nt<4;nt++){
                int row = rB + mt*16;
                int col = cB + nt*8;
                #pragma unroll
                for (int half=0; half<2; half++){
                    size_t o = (size_t)(m0 + row + half*8)*HIDN + n0 + col;
                    outp[o]   = acc[mt][nt][half*2+0];
                    outp[o+1] = acc[mt][nt][half*2+1];
                }
            }
        }
    }
}

// ---------------- RoPE + sigma ----------------
__global__ __launch_bounds__(256) void rope_kernel(const int* __restrict__ pos)
{
    int t = threadIdx.x;
    long rid = (long)blockIdx.x*2 + (t>>7);
    int d = t & 127;
    int s  = (int)(rid & (SS-1));
    int bh = (int)(rid >> 11);
    int b  = bh >> 4;
    size_t base = (size_t)rid * DD;
    float qv = g_sq[base+d], kv = g_sk[base+d];
    float qo = (d<64)? -g_sq[base+d+64] : g_sq[base+d-64];
    float ko = (d<64)? -g_sk[base+d+64] : g_sk[base+d-64];
    int p = pos[(size_t)b*SS + s];
    float inv = expf(-0.14391156831212787f * (float)(d & 63));
    float ang = (float)p * inv;
    float sn, cs;
    sincosf(ang, &sn, &cs);
    float qn = qv*cs + qo*sn;
    float kn = kv*cs + ko*sn;
    float sq = (qn>0.f) ? qn+1.f : expf(qn);
    float sk = (kn>0.f) ? kn+1.f : expf(kn);
    __syncthreads();
    g_sq[base+d] = sq;
    g_sk[base+d] = sk;
    __nv_bfloat16 h,l;
    bf16split(qn,h,l); g_qH[base+d]=h;  g_qL[base+d]=l;
    bf16split(kn,h,l); g_kH[base+d]=h;  g_kL[base+d]=l;
    bf16split(sq,h,l); g_sqH[base+d]=h; g_sqL[base+d]=l;
}

// ---------------- den[row] = dot(sig_q[row], z[h]) ----------------
__global__ __launch_bounds__(256) void den_kernel(const float* __restrict__ z)
{
    int wid = threadIdx.x>>5, lane = threadIdx.x&31;
    int row = blockIdx.x*8 + wid;
    int h = (row>>11)&15;
    const float4* sq = (const float4*)(g_sq + (size_t)row*DD);
    const float4* zz = (const float4*)(z + h*DD);
    float4 a = sq[lane], b = zz[lane];
    float dot = a.x*b.x + a.y*b.y + a.z*b.z + a.w*b.w;
    #pragma unroll
    for (int o=16;o>0;o>>=1) dot += __shfl_down_sync(0xffffffffu, dot, o);
    if (lane==0) g_den[row] = dot;
}

// ---------------- memory retrieval via HMMA ----------------
#define MR_TILE (128*136*2)
__global__ __launch_bounds__(256) void memret_mma_kernel()
{
    extern __shared__ char sm[];
    uint32_t sb = smem_u32(sm);
    float* denS = (float*)(sm + 4*MR_TILE);
    int s0 = blockIdx.x * 128;
    int bh = blockIdx.y;
    int h  = bh & 15;
    int t = threadIdx.x, wid=t>>5, lane=t&31;
    int wm = wid>>2, wn = wid&3;
    size_t rowbase = (size_t)bh*SS + s0;

    const uint4* srcs[4] = {
        (const uint4*)g_sqH + rowbase*16, (const uint4*)g_sqL + rowbase*16,
        (const uint4*)g_MtH + (size_t)h*2048, (const uint4*)g_MtL + (size_t)h*2048 };
    uint4* s4 = (uint4*)sm;
    #pragma unroll
    for (int i=0;i<32;i++){
        int slot = t + i*256;
        int sp = slot>>11, r = (slot>>4)&127, c16 = slot&15;
        s4[sp*(MR_TILE/16) + r*17 + c16] = srcs[sp][(size_t)r*16 + c16];
    }
    if (t < 128) denS[t] = g_den[rowbase + t];
    __syncthreads();

    float acc[4][4][4];
    #pragma unroll
    for (int mt=0;mt<4;mt++)
        #pragma unroll
        for (int nt=0;nt<4;nt++)
            #pragma unroll
            for (int e=0;e<4;e++) acc[mt][nt][e]=0.f;

    uint32_t aRow = (uint32_t)(wm*64 + (lane&15));
    uint32_t aChk = (uint32_t)(lane>>4);
    uint32_t bRow = (uint32_t)(wn*32 + (lane&7));
    uint32_t bChk = (uint32_t)((lane>>3)&1);

    #pragma unroll
    for (int kf=0; kf<8; kf++){
        uint32_t aH[4][4], aL[4][4], bH[4][2], bL[4][2];
        #pragma unroll
        for (int mt=0;mt<4;mt++){
            uint32_t off = (aRow + mt*16)*272u + (kf*2 + aChk)*16u;
            ldsm_x4(aH[mt][0],aH[mt][1],aH[mt][2],aH[mt][3], sb + 0*MR_TILE + off);
            ldsm_x4(aL[mt][0],aL[mt][1],aL[mt][2],aL[mt][3], sb + 1*MR_TILE + off);
        }
        #pragma unroll
        for (int nt=0;nt<4;nt++){
            uint32_t off = (bRow + nt*8)*272u + (kf*2 + bChk)*16u;
            ldsm_x2(bH[nt][0],bH[nt][1], sb + 2*MR_TILE + off);
            ldsm_x2(bL[nt][0],bL[nt][1], sb + 3*MR_TILE + off);
        }
        #pragma unroll
        for (int mt=0;mt<4;mt++)
            #pragma unroll
            for (int nt=0;nt<4;nt++){
                mma_bf16(acc[mt][nt], aH[mt], bH[nt]);
                mma_bf16(acc[mt][nt], aH[mt], bL[nt]);
                mma_bf16(acc[mt][nt], aL[mt], bH[nt]);
            }
    }

    int rB = wm*64 + (lane>>2);
    int cB = wn*32 + (lane&3)*2;
    size_t obase = ((size_t)bh*SS + s0)*DD;
    #pragma unroll
    for (int mt=0;mt<4;mt++)
        #pragma unroll
        for (int nt=0;nt<4;nt++)
            #pragma unroll
            for (int half=0; half<2; half++){
                int row = rB + mt*16 + half*8;
                int col = cB + nt*8;
                float dinv = 1.f/denS[row];
                g_mem[obase + (size_t)row*DD + col]   = acc[mt][nt][half*2+0]*dinv;
                g_mem[obase + (size_t)row*DD + col+1] = acc[mt][nt][half*2+1]*dinv;
            }
}

// ---------------- flash attention via HMMA, split precision ----------------
#define FQ_H 0
#define FQ_L 34816
#define FK_H 69632
#define FK_L 87040
#define FVT_H 104448
#define FVT_L 122880
#define FPS 141312
#define FP_H 174592
#define FP_L 193024
#define FMR 211456
#define FSCR 212992
#define FTOT 215040

__global__ __launch_bounds__(256,1) void attn_mma_kernel()
{
    extern __shared__ char sm[];
    uint32_t sb = smem_u32(sm);
    float* PS   = (float*)(sm + FPS);
    __nv_bfloat16* PH  = (__nv_bfloat16*)(sm + FP_H);
    __nv_bfloat16* PL  = (__nv_bfloat16*)(sm + FP_L);
    float* mrow = (float*)(sm + FMR);
    float* lrow = mrow + 128;
    float* rs   = lrow + 128;
    float* scrA = (float*)(sm + FSCR);
    float* scrB = scrA + 256;

    int qb = 15 - blockIdx.x;
    int bh = blockIdx.y;
    int t = threadIdx.x, wid=t>>5, lane=t&31;
    int wm = wid>>2, wn = wid&3;
    size_t rowbase = (size_t)bh*SS;
    size_t base = rowbase*DD;

    {
        uint4* s4 = (uint4*)sm;
        const uint4* q4[2] = { (const uint4*)g_qH + (rowbase + qb*128)*16,
                               (const uint4*)g_qL + (rowbase + qb*128)*16 };
        #pragma unroll
        for (int i=0;i<16;i++){
            int slot = t + i*256;
            int sp = slot>>11, r = (slot>>4)&127, c16 = slot&15;
            s4[(sp*34816)/16 + r*17 + c16] = q4[sp][(size_t)r*16 + c16];
        }
    }
    if (t < 128){ mrow[t] = -INFINITY; lrow[t] = 0.f; }

    float oacc[4][4][4];
    #pragma unroll
    for (int mt=0;mt<4;mt++)
        #pragma unroll
        for (int nt=0;nt<4;nt++)
            #pragma unroll
            for (int e=0;e<4;e++) oacc[mt][nt][e]=0.f;
    __syncthreads();

    const float sscale = 0.08838834764831845f;
    uint32_t aRow = (uint32_t)(wm*64 + (lane&15));
    uint32_t aChk = (uint32_t)(lane>>4);
    uint32_t bRowS = (uint32_t)(wn*16 + (lane&7));
    uint32_t bRowV = (uint32_t)(wn*32 + (lane&7));
    uint32_t bChk = (uint32_t)((lane>>3)&1);
    int rB = wm*64 + (lane>>2);
    int srow = t>>1, shalf = t&1;

    int jbmax = 2*qb + 1;
    for (int jb=0; jb<=jbmax; jb++){
        {
            uint4* s4 = (uint4*)(sm + FK_H);
            const uint4* k4[2] = { (const uint4*)g_kH + (rowbase + jb*64)*16,
                                   (const uint4*)g_kL + (rowbase + jb*64)*16 };
            #pragma unroll
            for (int i=0;i<8;i++){
                int slot = t + i*256;
                int sp = slot>>10, r = (slot>>4)&63, c16 = slot&15;
                s4[(sp*17408)/16 + r*17 + c16] = k4[sp][(size_t)r*16 + c16];
            }
        }
        #pragma unroll
        for (int i=0;i<8;i++){
            int slot = t + i*256;
            int sp = slot>>10, r = (slot>>3)&127, c = slot&7;
            const __nv_bfloat16* src = sp ? g_vTL : g_vTH;
            uint4 v = *(const uint4*)(src + (size_t)(bh*128+r)*2048 + jb*64 + c*8);
            *(uint4*)(sm + FVT_H + sp*18432 + r*144 + c*16) = v;
        }
        __syncthreads();

        float sacc[4][2][4];
        #pragma unroll
        for (int mt=0;mt<4;mt++)
            #pragma unroll
            for (int nt=0;nt<2;nt++)
                #pragma unroll
                for (int e=0;e<4;e++) sacc[mt][nt][e]=0.f;
        #pragma unroll
        for (int kf=0; kf<8; kf++){
            uint32_t aH[4][4], aL[4][4], bH[2][2], bL[2][2];
            #pragma unroll
            for (int mt=0;mt<4;mt++){
                uint32_t off = (aRow + mt*16)*272u + (kf*2 + aChk)*16u;
                ldsm_x4(aH[mt][0],aH[mt][1],aH[mt][2],aH[mt][3], sb + FQ_H + off);
                ldsm_x4(aL[mt][0],aL[mt][1],aL[mt][2],aL[mt][3], sb + FQ_L + off);
            }
            #pragma unroll
            for (int nt=0;nt<2;nt++){
                uint32_t off = (bRowS + nt*8)*272u + (kf*2 + bChk)*16u;
                ldsm_x2(bH[nt][0],bH[nt][1], sb + FK_H + off);
                ldsm_x2(bL[nt][0],bL[nt][1], sb + FK_L + off);
            }
            #pragma unroll
            for (int mt=0;mt<4;mt++)
                #pragma unroll
                for (int nt=0;nt<2;nt++){
                    mma_bf16(sacc[mt][nt], aH[mt], bH[nt]);
                    mma_bf16(sacc[mt][nt], aH[mt], bL[nt]);
                    mma_bf16(sacc[mt][nt], aL[mt], bH[nt]);
                }
        }
        {
            int cBs = wn*16 + (lane&3)*2;
            #pragma unroll
            for (int mt=0;mt<4;mt++)
                #pragma unroll
                for (int nt=0;nt<2;nt++)
                    #pragma unroll
                    for (int half=0; half<2; half++){
                        int row = rB + mt*16 + half*8;
                        int col = cBs + nt*8;
                        int qrow = qb*128 + row, kcol = jb*64 + col;
                        PS[row*65+col]   = (kcol   <= qrow) ? sacc[mt][nt][half*2+0]*sscale : -INFINITY;
                        PS[row*65+col+1] = (kcol+1 <= qrow) ? sacc[mt][nt][half*2+1]*sscale : -INFINITY;
                    }
        }
        __syncthreads();

        {
            float* PSrow = PS + srow*65 + shalf*32;
            float pm = -INFINITY;
            #pragma unroll 8
            for (int j=0;j<32;j++) pm = fmaxf(pm, PSrow[j]);
            scrA[t] = pm;
            __syncthreads();
            float m_new = fmaxf(mrow[srow], fmaxf(scrA[2*srow], scrA[2*srow+1]));
            float psum = 0.f;
            #pragma unroll 8
            for (int j=0;j<32;j++){
                float p = __expf(PSrow[j] - m_new);
                PSrow[j] = p;
                psum += p;
            }
            scrB[t] = psum;
            __syncthreads();
            if (t < 128){
                float mo = mrow[t];
                float mn = fmaxf(mo, fmaxf(scrA[2*t], scrA[2*t+1]));
                float sc = __expf(mo - mn);
                lrow[t] = sc*lrow[t] + scrB[2*t] + scrB[2*t+1];
                mrow[t] = mn;
                rs[t]   = sc;
            }
        }
        __syncthreads();

        #pragma unroll
        for (int i=0;i<32;i++){
            int e = i*256 + t;
            int row = e>>6, col = e&63;
            __nv_bfloat16 h,l; bf16split(PS[row*65+col], h, l);
            PH[row*72+col] = h; PL[row*72+col] = l;
        }
        __syncthreads();

        #pragma unroll
        for (int mt=0;mt<4;mt++){
            float s0 = rs[rB + mt*16], s1 = rs[rB + mt*16 + 8];
            #pragma unroll
            for (int nt=0;nt<4;nt++){
                oacc[mt][nt][0] *= s0; oacc[mt][nt][1] *= s0;
                oacc[mt][nt][2] *= s1; oacc[mt][nt][3] *= s1;
            }
        }
        #pragma unroll
        for (int kf=0; kf<4; kf++){
            uint32_t aH[4][4], aL[4][4], bH[4][2], bL[4][2];
            #pragma unroll
            for (int mt=0;mt<4;mt++){
                uint32_t off = (aRow + mt*16)*144u + (kf*2 + aChk)*16u;
                ldsm_x4(aH[mt][0],aH[mt][1],aH[mt][2],aH[mt][3], sb + FP_H + off);
                ldsm_x4(aL[mt][0],aL[mt][1],aL[mt][2],aL[mt][3], sb + FP_L + off);
            }
            #pragma unroll
            for (int nt=0;nt<4;nt++){
                uint32_t off = (bRowV + nt*8)*144u + (kf*2 + bChk)*16u;
                ldsm_x2(bH[nt][0],bH[nt][1], sb + FVT_H + off);
                ldsm_x2(bL[nt][0],bL[nt][1], sb + FVT_L + off);
            }
            #pragma unroll
            for (int mt=0;mt<4;mt++)
                #pragma unroll
                for (int nt=0;nt<4;nt++){
                    mma_bf16(oacc[mt][nt], aH[mt], bH[nt]);
                    mma_bf16(oacc[mt][nt], aH[mt], bL[nt]);
                    mma_bf16(oacc[mt][nt], aL[mt], bH[nt]);
                }
        }
        __syncthreads();
    }

    int cB = wn*32 + (lane&3)*2;
    #pragma unroll
    for (int mt=0;mt<4;mt++)
        #pragma unroll
        for (int half=0; half<2; half++){
            int row = rB + mt*16 + half*8;
            float linv = 1.f/lrow[row];
            #pragma unroll
            for (int nt=0;nt<4;nt++){
                int col = cB + nt*8;
                size_t o = base + (size_t)(qb*128+row)*DD + col;
                g_att[o]   = oacc[mt][nt][half*2+0]*linv;
                g_att[o+1] = oacc[mt][nt][half*2+1]*linv;
            }
        }
}

// ---------------- M update via HMMA (round-12 version) ----------------
__global__ __launch_bounds__(256) void m_update_mma_kernel()
{
    __shared__ __nv_bfloat16 skTH[128*40], skTL[128*40], vTH[128*40], vTL[128*40];
    __shared__ float zred[256];
    uint32_t sA_H = smem_u32(skTH), sA_L = smem_u32(skTL);
    uint32_t sB_H = smem_u32(vTH),  sB_L = smem_u32(vTL);

    int h = blockIdx.x, c = blockIdx.y;
    int b = c>>3, s0 = (c&7)*256;
    size_t base = (((size_t)(b*HH + h))*SS + s0)*DD;
    int t = threadIdx.x, wid=t>>5, lane=t&31;
    int wm = wid>>2, wn = wid&3;

    float acc[4][4][4];
    #pragma unroll
    for (int mt=0;mt<4;mt++)
        #pragma unroll
        for (int nt=0;nt<4;nt++)
            #pragma unroll
            for (int e=0;e<4;e++) acc[mt][nt][e]=0.f;
    float zacc = 0.f;

    uint32_t aRow = (uint32_t)(wm*64 + (lane&15));
    uint32_t aChk = (uint32_t)(lane>>4);
    uint32_t bRow = (uint32_t)(wn*32 + (lane&7));
    uint32_t bChk = (uint32_t)((lane>>3)&1);

    for (int kc=0; kc<8; kc++){
        #pragma unroll
        for (int i=0;i<16;i++){
            int e = i*256 + t;
            int s = e>>7, d = e&127;
            size_t g = base + (size_t)(kc*32+s)*DD + d;
            float sv = g_sk[g], vv = g_v[g];
            __nv_bfloat16 hh,ll;
            bf16split(sv,hh,ll); skTH[d*40+s]=hh; skTL[d*40+s]=ll;
            bf16split(vv,hh,ll); vTH[d*40+s]=hh;  vTL[d*40+s]=ll;
            zacc += sv;
        }
        __syncthreads();

        #pragma unroll
        for (int kf=0; kf<2; kf++){
            uint32_t aH[4][4], aL[4][4], bH[4][2], bL[4][2];
            #pragma unroll
            for (int mt=0;mt<4;mt++){
                uint32_t off = (aRow + mt*16)*80u + (kf*2 + aChk)*16u;
                ldsm_x4(aH[mt][0],aH[mt][1],aH[mt][2],aH[mt][3], sA_H + off);
                ldsm_x4(aL[mt][0],aL[mt][1],aL[mt][2],aL[mt][3], sA_L + off);
            }
            #pragma unroll
            for (int nt=0;nt<4;nt++){
                uint32_t off = (bRow + nt*8)*80u + (kf*2 + bChk)*16u;
                ldsm_x2(bH[nt][0],bH[nt][1], sB_H + off);
                ldsm_x2(bL[nt][0],bL[nt][1], sB_L + off);
            }
            #pragma unroll
            for (int mt=0;mt<4;mt++)
                #pragma unroll
                for (int nt=0;nt<4;nt++){
                    mma_bf16(acc[mt][nt], aH[mt], bH[nt]);
                    mma_bf16(acc[mt][nt], aH[mt], bL[nt]);
                    mma_bf16(acc[mt][nt], aL[mt], bH[nt]);
                }
        }
        __syncthreads();
    }

    zred[t] = zacc;
    __syncthreads();
    if (t < 128) g_zpart[(h*16 + c)*DD + t] = zred[t] + zred[t+128];

    size_t pbase = ((size_t)(h*16 + c)) << 14;
    int rB = wm*64 + (lane>>2);
    int cB = wn*32 + (lane&3)*2;
    #pragma unroll
    for (int mt=0;mt<4;mt++)
        #pragma unroll
        for (int nt=0;nt<4;nt++)
            #pragma unroll
            for (int half=0; half<2; half++){
                int row = rB + mt*16 + half*8;
                int col = cB + nt*8;
                g_mpart[pbase + (size_t)row*DD + col]   = acc[mt][nt][half*2+0];
                g_mpart[pbase + (size_t)row*DD + col+1] = acc[mt][nt][half*2+1];
            }
}

__global__ void reduce_m_kernel(const float* __restrict__ M, float* __restrict__ out)
{
    int idx = blockIdx.x*256 + threadIdx.x;
    int h = idx >> 14;
    int de = idx & 16383;
    float s = M[idx];
    #pragma unroll
    for (int c=0;c<16;c++) s += g_mpart[(((size_t)(h*16+c))<<14) + de];
    out[idx] = s;
}

__global__ void reduce_z_kernel(const float* __restrict__ z, float* __restrict__ out)
{
    int idx = blockIdx.x*256 + threadIdx.x;
    float s = z[idx];
    int h = idx >> 7, d = idx & 127;
    #pragma unroll
    for (int c=0;c<16;c++) s += g_zpart[(h*16+c)*DD + d];
    out[idx] = s;
}

// ---------------- launch ----------------
extern "C" void kernel_launch(void* const* d_in, const int* in_sizes, int n_in,
                              void* d_out, int out_size)
{
    (void)in_sizes; (void)n_in; (void)out_size;
    const float* hs   = (const float*)d_in[0];
    const float* Wq   = (const float*)d_in[1];
    const float* bq   = (const float*)d_in[2];
    const float* Wk   = (const float*)d_in[3];
    const float* bk   = (const float*)d_in[4];
    const float* Wv   = (const float*)d_in[5];
    const float* bv   = (const float*)d_in[6];
    const float* Wo   = (const float*)d_in[7];
    const float* beta = (const float*)d_in[8];
    const float* Mm   = (const float*)d_in[9];
    const float* zz   = (const float*)d_in[10];
    const int* pos    = (const int*)d_in[12];
    float* out = (float*)d_out;

    cudaFuncSetAttribute(attn_mma_kernel, cudaFuncAttributeMaxDynamicSharedMemorySize, FTOT);
    cudaFuncSetAttribute(memret_mma_kernel, cudaFuncAttributeMaxDynamicSharedMemorySize, 4*MR_TILE + 512);
    cudaFuncSetAttribute(gemm_mma_kernel, cudaFuncAttributeMaxDynamicSharedMemorySize, GEMM_SMEM);
    cudaFuncSetAttribute(vsplitT_kernel, cudaFuncAttributeMaxDynamicSharedMemorySize, VT_SMEM);

    split_a_kernel<<<MTOT*HIDN/256, 256>>>(hs);
    wsplit_kernel<<<dim3(64,64,4), 256>>>(Wq, Wk, Wv, Wo);
    msplit_kernel<<<1024, 256>>>(Mm);

    // QKV (q->g_sq staging, k->g_sk staging, v->g_v)
    gemm_mma_kernel<<<dim3(16,32,3), 256, GEMM_SMEM>>>(bq, bk, bv, nullptr, 0);

    rope_kernel<<<BHS/2, 256>>>(pos);

    vsplitT_kernel<<<dim3(32,16), 256, VT_SMEM>>>();

    den_kernel<<<BHS/8, 256>>>(zz);
    memret_mma_kernel<<<dim3(16,32), 256, 4*MR_TILE + 512>>>();

    attn_mma_kernel<<<dim3(16,32), 256, FTOT>>>();

    m_update_mma_kernel<<<dim3(16,16), 256>>>();
    reduce_m_kernel<<<1024, 256>>>(Mm, out + 8388608);
    reduce_z_kernel<<<8, 256>>>(zz, out + 8388608 + 262144);

    combine_split_kernel<<<MTOT*HIDN/256, 256>>>(beta);
    gemm_mma_kernel<<<dim3(16,32,1), 256, GEMM_SMEM>>>(bq, bk, bv, out, 1);
}

// round 16
// speedup vs baseline: 1.5763x; 1.0743x over previous
#include <cuda_runtime.h>
#include <cuda_bf16.h>
#include <math.h>
#include <stdint.h>

#define BB 2
#define SS 2048
#define HH 16
#define DD 128
#define HIDN 2048
#define BHS (BB*HH*SS)
#define MTOT 4096

// ---------------- scratch ----------------
__device__ float g_v  [BB*HH*SS*DD];
__device__ float g_sq [BB*HH*SS*DD];
__device__ float g_sk [BB*HH*SS*DD];
__device__ float g_mem[BB*HH*SS*DD];
__device__ float g_att[BB*HH*SS*DD];
__device__ float g_mpart[HH*16*DD*DD];
__device__ float g_zpart[HH*16*DD];

__device__ __nv_bfloat16 g_AH[MTOT*HIDN];
__device__ __nv_bfloat16 g_AL[MTOT*HIDN];
__device__ __nv_bfloat16 g_WtH[4u*HIDN*HIDN];
__device__ __nv_bfloat16 g_WtL[4u*HIDN*HIDN];
__device__ __nv_bfloat16 g_CH[MTOT*HIDN];
__device__ __nv_bfloat16 g_CL[MTOT*HIDN];
__device__ __nv_bfloat16 g_qH[BB*HH*SS*DD];
__device__ __nv_bfloat16 g_qL[BB*HH*SS*DD];
__device__ __nv_bfloat16 g_kH[BB*HH*SS*DD];
__device__ __nv_bfloat16 g_kL[BB*HH*SS*DD];
__device__ __nv_bfloat16 g_sqH[BB*HH*SS*DD];
__device__ __nv_bfloat16 g_sqL[BB*HH*SS*DD];
__device__ __nv_bfloat16 g_MtH[HH*DD*DD];
__device__ __nv_bfloat16 g_MtL[HH*DD*DD];
__device__ __nv_bfloat16 g_vTH[BB*HH*SS*DD];   // V^T [bh][d][s] splits
__device__ __nv_bfloat16 g_vTL[BB*HH*SS*DD];

// ================= mma.sync helpers =================
__device__ __forceinline__ uint32_t smem_u32(const void* p){
    return (uint32_t)__cvta_generic_to_shared(p);
}
__device__ __forceinline__ void ldsm_x4(uint32_t& r0, uint32_t& r1, uint32_t& r2, uint32_t& r3, uint32_t addr){
    asm volatile("ldmatrix.sync.aligned.m8n8.x4.shared.b16 {%0,%1,%2,%3}, [%4];"
        : "=r"(r0), "=r"(r1), "=r"(r2), "=r"(r3) : "r"(addr));
}
__device__ __forceinline__ void ldsm_x2(uint32_t& r0, uint32_t& r1, uint32_t addr){
    asm volatile("ldmatrix.sync.aligned.m8n8.x2.shared.b16 {%0,%1}, [%2];"
        : "=r"(r0), "=r"(r1) : "r"(addr));
}
__device__ __forceinline__ void mma_bf16(float* d, const uint32_t* a, const uint32_t* b){
    asm volatile("mma.sync.aligned.m16n8k16.row.col.f32.bf16.bf16.f32 "
        "{%0,%1,%2,%3}, {%4,%5,%6,%7}, {%8,%9}, {%0,%1,%2,%3};"
        : "+f"(d[0]), "+f"(d[1]), "+f"(d[2]), "+f"(d[3])
        : "r"(a[0]), "r"(a[1]), "r"(a[2]), "r"(a[3]), "r"(b[0]), "r"(b[1]));
}
__device__ __forceinline__ void bf16split(float v, __nv_bfloat16& h, __nv_bfloat16& l){
    h = __float2bfloat16_rn(v);
    l = __float2bfloat16_rn(v - __bfloat162float(h));
}
__device__ __forceinline__ void cp_async16(uint32_t smem_addr, const void* gptr){
    asm volatile("cp.async.cg.shared.global [%0], [%1], 16;" :: "r"(smem_addr), "l"(gptr));
}
#define CP_COMMIT() asm volatile("cp.async.commit_group;" ::: "memory")
#define CP_WAIT1()  asm volatile("cp.async.wait_group 1;" ::: "memory")
#define CP_WAIT0()  asm volatile("cp.async.wait_group 0;" ::: "memory")

// ================= pre-pass kernels =================
__global__ __launch_bounds__(256) void split_a_kernel(const float* __restrict__ A)
{
    int idx = blockIdx.x*256 + threadIdx.x;
    __nv_bfloat16 h,l; bf16split(A[idx], h, l);
    g_AH[idx] = h; g_AL[idx] = l;
}

__global__ __launch_bounds__(256) void wsplit_kernel(
    const float* __restrict__ Wq, const float* __restrict__ Wk,
    const float* __restrict__ Wv, const float* __restrict__ Wo)
{
    __shared__ float tile[32][33];
    int z = blockIdx.z;
    const float* W = (z==0)?Wq:((z==1)?Wk:((z==2)?Wv:Wo));
    __nv_bfloat16* H = g_WtH + (size_t)z*HIDN*HIDN;
    __nv_bfloat16* L = g_WtL + (size_t)z*HIDN*HIDN;
    int n0 = blockIdx.x*32, k0 = blockIdx.y*32;
    int tx = threadIdx.x & 31, ty = threadIdx.x >> 5;
    #pragma unroll
    for (int i=0;i<4;i++)
        tile[ty+8*i][tx] = W[(size_t)(k0+ty+8*i)*HIDN + n0+tx];
    __syncthreads();
    #pragma unroll
    for (int i=0;i<4;i++){
        __nv_bfloat16 h,l; bf16split(tile[tx][ty+8*i], h, l);
        size_t o = (size_t)(n0+ty+8*i)*HIDN + k0+tx;
        H[o] = h; L[o] = l;
    }
}

__global__ __launch_bounds__(256) void msplit_kernel(const float* __restrict__ M)
{
    int idx = blockIdx.x*256 + threadIdx.x;
    int h = idx >> 14, d = (idx>>7)&127, e = idx&127;
    __nv_bfloat16 hh,ll; bf16split(M[idx], hh, ll);
    size_t o = (size_t)h*16384 + e*128 + d;
    g_MtH[o] = hh; g_MtL[o] = ll;
}

__global__ __launch_bounds__(256) void combine_split_kernel(const float* __restrict__ beta)
{
    int idx = blockIdx.x*256 + threadIdx.x;
    float g = 1.f/(1.f + expf(-beta[0]));
    int m = idx >> 11, kcol = idx & 2047;
    int b = m>>11, s = m&2047, h = kcol>>7, d = kcol&127;
    size_t a = (((size_t)(b*HH+h))*SS + s)*DD + d;
    float v = g*g_mem[a] + (1.f-g)*g_att[a];
    __nv_bfloat16 hh,ll; bf16split(v, hh, ll);
    g_CH[idx] = hh; g_CL[idx] = ll;
}

// transpose+split V: [bh][s][d] fp32 -> [bh][d][s] bf16 H/L.
#define VT_SMEM (2*128*66*4)
__global__ __launch_bounds__(256) void vsplitT_kernel()
{
    extern __shared__ char sm[];
    uint32_t* sH = (uint32_t*)sm;            // [128 d][66]
    uint32_t* sL = sH + 128*66;
    int bh = blockIdx.x, sc0 = blockIdx.y*128;
    int t = threadIdx.x;
    size_t base = ((size_t)bh*SS + sc0)*DD;
    #pragma unroll
    for (int i=0;i<32;i++){
        int pidx = i*256 + t;
        int d = pidx & 127, sp = pidx >> 7;
        float v0 = g_v[base + (size_t)(2*sp)*DD + d];
        float v1 = g_v[base + (size_t)(2*sp+1)*DD + d];
        __nv_bfloat16 h0,l0,h1,l1;
        bf16split(v0,h0,l0); bf16split(v1,h1,l1);
        uint32_t ph = ((uint32_t)__bfloat16_as_ushort(h1)<<16) | (uint32_t)__bfloat16_as_ushort(h0);
        uint32_t pl = ((uint32_t)__bfloat16_as_ushort(l1)<<16) | (uint32_t)__bfloat16_as_ushort(l0);
        sH[d*66 + sp] = ph;
        sL[d*66 + sp] = pl;
    }
    __syncthreads();
    #pragma unroll
    for (int i=0;i<16;i++){
        int flat = i*256 + t;
        int d = flat>>5, c2 = flat&31;
        uint2 vh = *(uint2*)&sH[d*66 + c2*2];
        uint2 vl = *(uint2*)&sL[d*66 + c2*2];
        size_t o32 = ((size_t)(bh*128+d)*2048 + sc0)/2 + c2*2;
        *(uint2*)((uint32_t*)g_vTH + o32) = vh;
        *(uint2*)((uint32_t*)g_vTL + o32) = vl;
    }
}

// ================= HMMA GEMM: cp.async 2-stage (round-12) + B ldsm_x4 =================
#define TSTRIDE 40
#define TILE_BF16 (128*TSTRIDE)
#define TILE_U4   (TILE_BF16/8)
#define BUF_BYTES (4*TILE_BF16*2)      // 40960 per stage
#define GEMM_SMEM (2*BUF_BYTES)        // 81920

__global__ __launch_bounds__(256,2) void gemm_mma_kernel(
    const float* __restrict__ bq, const float* __restrict__ bk, const float* __restrict__ bv,
    float* __restrict__ outp, int asel)
{
    extern __shared__ char sm[];
    uint32_t sbase = smem_u32(sm);

    int t = threadIdx.x;
    int wid = t>>5, lane = t&31;
    int wm = wid>>2, wn = wid&3;
    int n0 = blockIdx.x*128;
    int m0 = blockIdx.y*128;
    int which = (asel==0) ? blockIdx.z : 3;
    const __nv_bfloat16* Ah = (asel==0) ? g_AH : g_CH;
    const __nv_bfloat16* Al = (asel==0) ? g_AL : g_CL;
    const __nv_bfloat16* Bh = g_WtH + (size_t)which*HIDN*HIDN;
    const __nv_bfloat16* Bl = g_WtL + (size_t)which*HIDN*HIDN;

    const __nv_bfloat16* gsrc[4] = {
        Ah + (size_t)m0*HIDN, Al + (size_t)m0*HIDN,
        Bh + (size_t)n0*HIDN, Bl + (size_t)n0*HIDN };

    const __nv_bfloat16* gp[8];
    uint32_t soff[8];
    #pragma unroll
    for (int i=0;i<8;i++){
        int slot = t + i*256;
        int tt = slot>>9;
        int w = slot&511;
        int rr = w>>2, cc = w&3;
        gp[i] = gsrc[tt] + (size_t)rr*HIDN + cc*8;
        soff[i] = (uint32_t)(tt*TILE_U4 + rr*5 + cc)*16u;
    }

    float acc[4][4][4];
    #pragma unroll
    for (int mt=0;mt<4;mt++)
        #pragma unroll
        for (int nt=0;nt<4;nt++)
            #pragma unroll
            for (int e=0;e<4;e++) acc[mt][nt][e] = 0.f;

    uint32_t aRow = (uint32_t)(wm*64 + (lane&15));
    uint32_t aChk = (uint32_t)(lane>>4);
    // B ldsm_x4 lane map: matrices (pair*2, pair*2+1), k-low/k-high
    uint32_t bRow4 = (uint32_t)(wn*32 + ((lane>>4)<<3) + (lane&7));
    uint32_t bChk4 = (uint32_t)((lane>>3)&1);

    #pragma unroll
    for (int i=0;i<8;i++) cp_async16(sbase + soff[i], gp[i]);
    CP_COMMIT();
    #pragma unroll
    for (int i=0;i<8;i++) cp_async16(sbase + BUF_BYTES + soff[i], gp[i] + 32);
    CP_COMMIT();

    for (int kt=0; kt<64; kt++){
        int cur = kt & 1;
        if (kt == 63) { CP_WAIT0(); } else { CP_WAIT1(); }
        __syncthreads();

        uint32_t bufb = sbase + (uint32_t)cur*BUF_BYTES;
        #pragma unroll
        for (int k16=0;k16<2;k16++){
            uint32_t aH[4][4], aL[4][4], bH[4][2], bL[4][2];
            #pragma unroll
            for (int mt=0;mt<4;mt++){
                uint32_t off = (aRow + mt*16)*80u + (k16*2 + aChk)*16u;
                ldsm_x4(aH[mt][0],aH[mt][1],aH[mt][2],aH[mt][3], bufb + 0*TILE_BF16*2 + off);
                ldsm_x4(aL[mt][0],aL[mt][1],aL[mt][2],aL[mt][3], bufb + 1*TILE_BF16*2 + off);
            }
            #pragma unroll
            for (int pair=0;pair<2;pair++){
                uint32_t off = (bRow4 + pair*16)*80u + (k16*2 + bChk4)*16u;
                ldsm_x4(bH[pair*2][0],bH[pair*2][1],bH[pair*2+1][0],bH[pair*2+1][1],
                        bufb + 2*TILE_BF16*2 + off);
                ldsm_x4(bL[pair*2][0],bL[pair*2][1],bL[pair*2+1][0],bL[pair*2+1][1],
                        bufb + 3*TILE_BF16*2 + off);
            }
            #pragma unroll
            for (int mt=0;mt<4;mt++)
                #pragma unroll
                for (int nt=0;nt<4;nt++){
                    mma_bf16(acc[mt][nt], aH[mt], bH[nt]);
                    mma_bf16(acc[mt][nt], aH[mt], bL[nt]);
                    mma_bf16(acc[mt][nt], aL[mt], bH[nt]);
                }
        }
        if (kt < 62){
            __syncthreads();
            int k0 = (kt+2)*32;
            #pragma unroll
            for (int i=0;i<8;i++) cp_async16(sbase + (uint32_t)cur*BUF_BYTES + soff[i], gp[i] + k0);
            CP_COMMIT();
        }
    }

    int rB = wm*64 + (lane>>2);
    int cB = wn*32 + (lane&3)*2;
    if (asel == 0){
        const float* bias = (which==0)?bq:((which==1)?bk:bv);
        int h = n0>>7;
        #pragma unroll
        for (int mt=0;mt<4;mt++){
            #pragma unroll
            for (int nt=0;nt<4;nt++){
                int row = rB + mt*16;
                int col = cB + nt*8;
                int n = n0 + col;
                #pragma unroll
                for (int half=0; half<2; half++){
                    int m = m0 + row + half*8;
                    int b = m>>11, s = m&2047;
                    size_t o = (((size_t)(b*HH+h))*SS + s)*DD + col;
                    float v0 = acc[mt][nt][half*2+0] + bias[n];
                    float v1 = acc[mt][nt][half*2+1] + bias[n+1];
                    if (which == 2){
                        g_v[o] = v0; g_v[o+1] = v1;
                    } else {
                        float* O = (which==0)?g_sq:g_sk;
                        O[o] = v0; O[o+1] = v1;
                    }
                }
            }
        }
    } else {
        #pragma unroll
        for (int mt=0;mt<4;mt++){
            #pragma unroll
            for (int nt=0;nt<4;nt++){
                int row = rB + mt*16;
                int col = cB + nt*8;
                #pragma unroll
                for (int half=0; half<2; half++){
                    size_t o = (size_t)(m0 + row + half*8)*HIDN + n0 + col;
                    outp[o]   = acc[mt][nt][half*2+0];
                    outp[o+1] = acc[mt][nt][half*2+1];
                }
            }
        }
    }
}

// ---------------- RoPE + sigma ----------------
__global__ __launch_bounds__(256) void rope_kernel(const int* __restrict__ pos)
{
    int t = threadIdx.x;
    long rid = (long)blockIdx.x*2 + (t>>7);
    int d = t & 127;
    int s  = (int)(rid & (SS-1));
    int bh = (int)(rid >> 11);
    int b  = bh >> 4;
    size_t base = (size_t)rid * DD;
    float qv = g_sq[base+d], kv = g_sk[base+d];
    float qo = (d<64)? -g_sq[base+d+64] : g_sq[base+d-64];
    float ko = (d<64)? -g_sk[base+d+64] : g_sk[base+d-64];
    int p = pos[(size_t)b*SS + s];
    float inv = expf(-0.14391156831212787f * (float)(d & 63));
    float ang = (float)p * inv;
    float sn, cs;
    sincosf(ang, &sn, &cs);
    float qn = qv*cs + qo*sn;
    float kn = kv*cs + ko*sn;
    float sq = (qn>0.f) ? qn+1.f : expf(qn);
    float sk = (kn>0.f) ? kn+1.f : expf(kn);
    __syncthreads();
    g_sq[base+d] = sq;
    g_sk[base+d] = sk;
    __nv_bfloat16 h,l;
    bf16split(qn,h,l); g_qH[base+d]=h;  g_qL[base+d]=l;
    bf16split(kn,h,l); g_kH[base+d]=h;  g_kL[base+d]=l;
    bf16split(sq,h,l); g_sqH[base+d]=h; g_sqL[base+d]=l;
}

// ---------------- memory retrieval via HMMA, den computed in-kernel ----------------
#define MR_TILE (128*136*2)
__global__ __launch_bounds__(256) void memret_mma_kernel(const float* __restrict__ z)
{
    extern __shared__ char sm[];
    uint32_t sb = smem_u32(sm);
    float* denS = (float*)(sm + 4*MR_TILE);
    int s0 = blockIdx.x * 128;
    int bh = blockIdx.y;
    int h  = bh & 15;
    int t = threadIdx.x, wid=t>>5, lane=t&31;
    int wm = wid>>2, wn = wid&3;
    size_t rowbase = (size_t)bh*SS + s0;

    const uint4* srcs[4] = {
        (const uint4*)g_sqH + rowbase*16, (const uint4*)g_sqL + rowbase*16,
        (const uint4*)g_MtH + (size_t)h*2048, (const uint4*)g_MtL + (size_t)h*2048 };
    uint4* s4 = (uint4*)sm;
    #pragma unroll
    for (int i=0;i<32;i++){
        int slot = t + i*256;
        int sp = slot>>11, r = (slot>>4)&127, c16 = slot&15;
        s4[sp*(MR_TILE/16) + r*17 + c16] = srcs[sp][(size_t)r*16 + c16];
    }
    // den for our 128 rows: warp-per-16-rows dot(sig_q[row], z[h])
    {
        const float4* zz = (const float4*)(z + h*DD);
        float4 bz = zz[lane];
        #pragma unroll
        for (int i=0;i<16;i++){
            int rr = wid*16 + i;
            const float4* sq = (const float4*)(g_sq + (rowbase + rr)*DD);
            float4 a = sq[lane];
            float dot = a.x*bz.x + a.y*bz.y + a.z*bz.z + a.w*bz.w;
            #pragma unroll
            for (int o=16;o>0;o>>=1) dot += __shfl_down_sync(0xffffffffu, dot, o);
            if (lane==0) denS[rr] = dot;
        }
    }
    __syncthreads();

    float acc[4][4][4];
    #pragma unroll
    for (int mt=0;mt<4;mt++)
        #pragma unroll
        for (int nt=0;nt<4;nt++)
            #pragma unroll
            for (int e=0;e<4;e++) acc[mt][nt][e]=0.f;

    uint32_t aRow = (uint32_t)(wm*64 + (lane&15));
    uint32_t aChk = (uint32_t)(lane>>4);
    uint32_t bRow = (uint32_t)(wn*32 + (lane&7));
    uint32_t bChk = (uint32_t)((lane>>3)&1);

    #pragma unroll
    for (int kf=0; kf<8; kf++){
        uint32_t aH[4][4], aL[4][4], bH[4][2], bL[4][2];
        #pragma unroll
        for (int mt=0;mt<4;mt++){
            uint32_t off = (aRow + mt*16)*272u + (kf*2 + aChk)*16u;
            ldsm_x4(aH[mt][0],aH[mt][1],aH[mt][2],aH[mt][3], sb + 0*MR_TILE + off);
            ldsm_x4(aL[mt][0],aL[mt][1],aL[mt][2],aL[mt][3], sb + 1*MR_TILE + off);
        }
        #pragma unroll
        for (int nt=0;nt<4;nt++){
            uint32_t off = (bRow + nt*8)*272u + (kf*2 + bChk)*16u;
            ldsm_x2(bH[nt][0],bH[nt][1], sb + 2*MR_TILE + off);
            ldsm_x2(bL[nt][0],bL[nt][1], sb + 3*MR_TILE + off);
        }
        #pragma unroll
        for (int mt=0;mt<4;mt++)
            #pragma unroll
            for (int nt=0;nt<4;nt++){
                mma_bf16(acc[mt][nt], aH[mt], bH[nt]);
                mma_bf16(acc[mt][nt], aH[mt], bL[nt]);
                mma_bf16(acc[mt][nt], aL[mt], bH[nt]);
            }
    }

    int rB = wm*64 + (lane>>2);
    int cB = wn*32 + (lane&3)*2;
    size_t obase = ((size_t)bh*SS + s0)*DD;
    #pragma unroll
    for (int mt=0;mt<4;mt++)
        #pragma unroll
        for (int nt=0;nt<4;nt++)
            #pragma unroll
            for (int half=0; half<2; half++){
                int row = rB + mt*16 + half*8;
                int col = cB + nt*8;
                float dinv = 1.f/denS[row];
                g_mem[obase + (size_t)row*DD + col]   = acc[mt][nt][half*2+0]*dinv;
                g_mem[obase + (size_t)row*DD + col+1] = acc[mt][nt][half*2+1]*dinv;
            }
}

// ---------------- flash attention via HMMA, split precision (round-12) ----------------
#define FQ_H 0
#define FQ_L 34816
#define FK_H 69632
#define FK_L 87040
#define FVT_H 104448
#define FVT_L 122880
#define FPS 141312
#define FP_H 174592
#define FP_L 193024
#define FMR 211456
#define FSCR 212992
#define FTOT 215040

__global__ __launch_bounds__(256,1) void attn_mma_kernel()
{
    extern __shared__ char sm[];
    uint32_t sb = smem_u32(sm);
    float* PS   = (float*)(sm + FPS);
    __nv_bfloat16* PH  = (__nv_bfloat16*)(sm + FP_H);
    __nv_bfloat16* PL  = (__nv_bfloat16*)(sm + FP_L);
    float* mrow = (float*)(sm + FMR);
    float* lrow = mrow + 128;
    float* rs   = lrow + 128;
    float* scrA = (float*)(sm + FSCR);
    float* scrB = scrA + 256;

    int qb = 15 - blockIdx.x;
    int bh = blockIdx.y;
    int t = threadIdx.x, wid=t>>5, lane=t&31;
    int wm = wid>>2, wn = wid&3;
    size_t rowbase = (size_t)bh*SS;
    size_t base = rowbase*DD;

    {
        uint4* s4 = (uint4*)sm;
        const uint4* q4[2] = { (const uint4*)g_qH + (rowbase + qb*128)*16,
                               (const uint4*)g_qL + (rowbase + qb*128)*16 };
        #pragma unroll
        for (int i=0;i<16;i++){
            int slot = t + i*256;
            int sp = slot>>11, r = (slot>>4)&127, c16 = slot&15;
            s4[(sp*34816)/16 + r*17 + c16] = q4[sp][(size_t)r*16 + c16];
        }
    }
    if (t < 128){ mrow[t] = -INFINITY; lrow[t] = 0.f; }

    float oacc[4][4][4];
    #pragma unroll
    for (int mt=0;mt<4;mt++)
        #pragma unroll
        for (int nt=0;nt<4;nt++)
            #pragma unroll
            for (int e=0;e<4;e++) oacc[mt][nt][e]=0.f;
    __syncthreads();

    const float sscale = 0.08838834764831845f;
    uint32_t aRow = (uint32_t)(wm*64 + (lane&15));
    uint32_t aChk = (uint32_t)(lane>>4);
    uint32_t bRowS = (uint32_t)(wn*16 + (lane&7));
    uint32_t bRowV = (uint32_t)(wn*32 + (lane&7));
    uint32_t bChk = (uint32_t)((lane>>3)&1);
    int rB = wm*64 + (lane>>2);
    int srow = t>>1, shalf = t&1;

    int jbmax = 2*qb + 1;
    for (int jb=0; jb<=jbmax; jb++){
        {
            uint4* s4 = (uint4*)(sm + FK_H);
            const uint4* k4[2] = { (const uint4*)g_kH + (rowbase + jb*64)*16,
                                   (const uint4*)g_kL + (rowbase + jb*64)*16 };
            #pragma unroll
            for (int i=0;i<8;i++){
                int slot = t + i*256;
                int sp = slot>>10, r = (slot>>4)&63, c16 = slot&15;
                s4[(sp*17408)/16 + r*17 + c16] = k4[sp][(size_t)r*16 + c16];
            }
        }
        #pragma unroll
        for (int i=0;i<8;i++){
            int slot = t + i*256;
            int sp = slot>>10, r = (slot>>3)&127, c = slot&7;
            const __nv_bfloat16* src = sp ? g_vTL : g_vTH;
            uint4 v = *(const uint4*)(src + (size_t)(bh*128+r)*2048 + jb*64 + c*8);
            *(uint4*)(sm + FVT_H + sp*18432 + r*144 + c*16) = v;
        }
        __syncthreads();

        float sacc[4][2][4];
        #pragma unroll
        for (int mt=0;mt<4;mt++)
            #pragma unroll
            for (int nt=0;nt<2;nt++)
                #pragma unroll
                for (int e=0;e<4;e++) sacc[mt][nt][e]=0.f;
        #pragma unroll
        for (int kf=0; kf<8; kf++){
            uint32_t aH[4][4], aL[4][4], bH[2][2], bL[2][2];
            #pragma unroll
            for (int mt=0;mt<4;mt++){
                uint32_t off = (aRow + mt*16)*272u + (kf*2 + aChk)*16u;
                ldsm_x4(aH[mt][0],aH[mt][1],aH[mt][2],aH[mt][3], sb + FQ_H + off);
                ldsm_x4(aL[mt][0],aL[mt][1],aL[mt][2],aL[mt][3], sb + FQ_L + off);
            }
            #pragma unroll
            for (int nt=0;nt<2;nt++){
                uint32_t off = (bRowS + nt*8)*272u + (kf*2 + bChk)*16u;
                ldsm_x2(bH[nt][0],bH[nt][1], sb + FK_H + off);
                ldsm_x2(bL[nt][0],bL[nt][1], sb + FK_L + off);
            }
            #pragma unroll
            for (int mt=0;mt<4;mt++)
                #pragma unroll
                for (int nt=0;nt<2;nt++){
                    mma_bf16(sacc[mt][nt], aH[mt], bH[nt]);
                    mma_bf16(sacc[mt][nt], aH[mt], bL[nt]);
                    mma_bf16(sacc[mt][nt], aL[mt], bH[nt]);
                }
        }
        {
            int cBs = wn*16 + (lane&3)*2;
            #pragma unroll
            for (int mt=0;mt<4;mt++)
                #pragma unroll
                for (int nt=0;nt<2;nt++)
                    #pragma unroll
                    for (int half=0; half<2; half++){
                        int row = rB + mt*16 + half*8;
                        int col = cBs + nt*8;
                        int qrow = qb*128 + row, kcol = jb*64 + col;
                        PS[row*65+col]   = (kcol   <= qrow) ? sacc[mt][nt][half*2+0]*sscale : -INFINITY;
                        PS[row*65+col+1] = (kcol+1 <= qrow) ? sacc[mt][nt][half*2+1]*sscale : -INFINITY;
                    }
        }
        __syncthreads();

        {
            float* PSrow = PS + srow*65 + shalf*32;
            float pm = -INFINITY;
            #pragma unroll 8
            for (int j=0;j<32;j++) pm = fmaxf(pm, PSrow[j]);
            scrA[t] = pm;
            __syncthreads();
            float m_new = fmaxf(mrow[srow], fmaxf(scrA[2*srow], scrA[2*srow+1]));
            float psum = 0.f;
            #pragma unroll 8
            for (int j=0;j<32;j++){
                float p = __expf(PSrow[j] - m_new);
                PSrow[j] = p;
                psum += p;
            }
            scrB[t] = psum;
            __syncthreads();
            if (t < 128){
                float mo = mrow[t];
                float mn = fmaxf(mo, fmaxf(scrA[2*t], scrA[2*t+1]));
                float sc = __expf(mo - mn);
                lrow[t] = sc*lrow[t] + scrB[2*t] + scrB[2*t+1];
                mrow[t] = mn;
                rs[t]   = sc;
            }
        }
        __syncthreads();

        #pragma unroll
        for (int i=0;i<32;i++){
            int e = i*256 + t;
            int row = e>>6, col = e&63;
            __nv_bfloat16 h,l; bf16split(PS[row*65+col], h, l);
            PH[row*72+col] = h; PL[row*72+col] = l;
        }
        __syncthreads();

        #pragma unroll
        for (int mt=0;mt<4;mt++){
            float s0 = rs[rB + mt*16], s1 = rs[rB + mt*16 + 8];
            #pragma unroll
            for (int nt=0;nt<4;nt++){
                oacc[mt][nt][0] *= s0; oacc[mt][nt][1] *= s0;
                oacc[mt][nt][2] *= s1; oacc[mt][nt][3] *= s1;
            }
        }
        #pragma unroll
        for (int kf=0; kf<4; kf++){
            uint32_t aH[4][4], aL[4][4], bH[4][2], bL[4][2];
            #pragma unroll
            for (int mt=0;mt<4;mt++){
                uint32_t off = (aRow + mt*16)*144u + (kf*2 + aChk)*16u;
                ldsm_x4(aH[mt][0],aH[mt][1],aH[mt][2],aH[mt][3], sb + FP_H + off);
                ldsm_x4(aL[mt][0],aL[mt][1],aL[mt][2],aL[mt][3], sb + FP_L + off);
            }
            #pragma unroll
            for (int nt=0;nt<4;nt++){
                uint32_t off = (bRowV + nt*8)*144u + (kf*2 + bChk)*16u;
                ldsm_x2(bH[nt][0],bH[nt][1], sb + FVT_H + off);
                ldsm_x2(bL[nt][0],bL[nt][1], sb + FVT_L + off);
            }
            #pragma unroll
            for (int mt=0;mt<4;mt++)
                #pragma unroll
                for (int nt=0;nt<4;nt++){
                    mma_bf16(oacc[mt][nt], aH[mt], bH[nt]);
                    mma_bf16(oacc[mt][nt], aH[mt], bL[nt]);
                    mma_bf16(oacc[mt][nt], aL[mt], bH[nt]);
                }
        }
        __syncthreads();
    }

    int cB = wn*32 + (lane&3)*2;
    #pragma unroll
    for (int mt=0;mt<4;mt++)
        #pragma unroll
        for (int half=0; half<2; half++){
            int row = rB + mt*16 + half*8;
            float linv = 1.f/lrow[row];
            #pragma unroll
            for (int nt=0;nt<4;nt++){
                int col = cB + nt*8;
                size_t o = base + (size_t)(qb*128+row)*DD + col;
                g_att[o]   = oacc[mt][nt][half*2+0]*linv;
                g_att[o+1] = oacc[mt][nt][half*2+1]*linv;
            }
        }
}

// ---------------- M update via HMMA (round-12) ----------------
__global__ __launch_bounds__(256) void m_update_mma_kernel()
{
    __shared__ __nv_bfloat16 skTH[128*40], skTL[128*40], vTH[128*40], vTL[128*40];
    __shared__ float zred[256];
    uint32_t sA_H = smem_u32(skTH), sA_L = smem_u32(skTL);
    uint32_t sB_H = smem_u32(vTH),  sB_L = smem_u32(vTL);

    int h = blockIdx.x, c = blockIdx.y;
    int b = c>>3, s0 = (c&7)*256;
    size_t base = (((size_t)(b*HH + h))*SS + s0)*DD;
    int t = threadIdx.x, wid=t>>5, lane=t&31;
    int wm = wid>>2, wn = wid&3;

    float acc[4][4][4];
    #pragma unroll
    for (int mt=0;mt<4;mt++)
        #pragma unroll
        for (int nt=0;nt<4;nt++)
            #pragma unroll
            for (int e=0;e<4;e++) acc[mt][nt][e]=0.f;
    float zacc = 0.f;

    uint32_t aRow = (uint32_t)(wm*64 + (lane&15));
    uint32_t aChk = (uint32_t)(lane>>4);
    uint32_t bRow = (uint32_t)(wn*32 + (lane&7));
    uint32_t bChk = (uint32_t)((lane>>3)&1);

    for (int kc=0; kc<8; kc++){
        #pragma unroll
        for (int i=0;i<16;i++){
            int e = i*256 + t;
            int s = e>>7, d = e&127;
            size_t g = base + (size_t)(kc*32+s)*DD + d;
            float sv = g_sk[g], vv = g_v[g];
            __nv_bfloat16 hh,ll;
            bf16split(sv,hh,ll); skTH[d*40+s]=hh; skTL[d*40+s]=ll;
            bf16split(vv,hh,ll); vTH[d*40+s]=hh;  vTL[d*40+s]=ll;
            zacc += sv;
        }
        __syncthreads();

        #pragma unroll
        for (int kf=0; kf<2; kf++){
            uint32_t aH[4][4], aL[4][4], bH[4][2], bL[4][2];
            #pragma unroll
            for (int mt=0;mt<4;mt++){
                uint32_t off = (aRow + mt*16)*80u + (kf*2 + aChk)*16u;
                ldsm_x4(aH[mt][0],aH[mt][1],aH[mt][2],aH[mt][3], sA_H + off);
                ldsm_x4(aL[mt][0],aL[mt][1],aL[mt][2],aL[mt][3], sA_L + off);
            }
            #pragma unroll
            for (int nt=0;nt<4;nt++){
                uint32_t off = (bRow + nt*8)*80u + (kf*2 + bChk)*16u;
                ldsm_x2(bH[nt][0],bH[nt][1], sB_H + off);
                ldsm_x2(bL[nt][0],bL[nt][1], sB_L + off);
            }
            #pragma unroll
            for (int mt=0;mt<4;mt++)
                #pragma unroll
                for (int nt=0;nt<4;nt++){
                    mma_bf16(acc[mt][nt], aH[mt], bH[nt]);
                    mma_bf16(acc[mt][nt], aH[mt], bL[nt]);
                    mma_bf16(acc[mt][nt], aL[mt], bH[nt]);
                }
        }
        __syncthreads();
    }

    zred[t] = zacc;
    __syncthreads();
    if (t < 128) g_zpart[(h*16 + c)*DD + t] = zred[t] + zred[t+128];

    size_t pbase = ((size_t)(h*16 + c)) << 14;
    int rB = wm*64 + (lane>>2);
    int cB = wn*32 + (lane&3)*2;
    #pragma unroll
    for (int mt=0;mt<4;mt++)
        #pragma unroll
        for (int nt=0;nt<4;nt++)
            #pragma unroll
            for (int half=0; half<2; half++){
                int row = rB + mt*16 + half*8;
                int col = cB + nt*8;
                g_mpart[pbase + (size_t)row*DD + col]   = acc[mt][nt][half*2+0];
                g_mpart[pbase + (size_t)row*DD + col+1] = acc[mt][nt][half*2+1];
            }
}

__global__ void reduce_m_kernel(const float* __restrict__ M, float* __restrict__ out)
{
    int idx = blockIdx.x*256 + threadIdx.x;
    int h = idx >> 14;
    int de = idx & 16383;
    float s = M[idx];
    #pragma unroll
    for (int c=0;c<16;c++) s += g_mpart[(((size_t)(h*16+c))<<14) + de];
    out[idx] = s;
}

__global__ void reduce_z_kernel(const float* __restrict__ z, float* __restrict__ out)
{
    int idx = blockIdx.x*256 + threadIdx.x;
    float s = z[idx];
    int h = idx >> 7, d = idx & 127;
    #pragma unroll
    for (int c=0;c<16;c++) s += g_zpart[(h*16+c)*DD + d];
    out[idx] = s;
}

// ---------------- launch ----------------
extern "C" void kernel_launch(void* const* d_in, const int* in_sizes, int n_in,
                              void* d_out, int out_size)
{
    (void)in_sizes; (void)n_in; (void)out_size;
    const float* hs   = (const float*)d_in[0];
    const float* Wq   = (const float*)d_in[1];
    const float* bq   = (const float*)d_in[2];
    const float* Wk   = (const float*)d_in[3];
    const float* bk   = (const float*)d_in[4];
    const float* Wv   = (const float*)d_in[5];
    const float* bv   = (const float*)d_in[6];
    const float* Wo   = (const float*)d_in[7];
    const float* beta = (const float*)d_in[8];
    const float* Mm   = (const float*)d_in[9];
    const float* zz   = (const float*)d_in[10];
    const int* pos    = (const int*)d_in[12];
    float* out = (float*)d_out;

    cudaFuncSetAttribute(attn_mma_kernel, cudaFuncAttributeMaxDynamicSharedMemorySize, FTOT);
    cudaFuncSetAttribute(memret_mma_kernel, cudaFuncAttributeMaxDynamicSharedMemorySize, 4*MR_TILE + 512);
    cudaFuncSetAttribute(gemm_mma_kernel, cudaFuncAttributeMaxDynamicSharedMemorySize, GEMM_SMEM);
    cudaFuncSetAttribute(vsplitT_kernel, cudaFuncAttributeMaxDynamicSharedMemorySize, VT_SMEM);

    split_a_kernel<<<MTOT*HIDN/256, 256>>>(hs);
    wsplit_kernel<<<dim3(64,64,4), 256>>>(Wq, Wk, Wv, Wo);
    msplit_kernel<<<1024, 256>>>(Mm);

    // QKV (q->g_sq staging, k->g_sk staging, v->g_v)
    gemm_mma_kernel<<<dim3(16,32,3), 256, GEMM_SMEM>>>(bq, bk, bv, nullptr, 0);

    rope_kernel<<<BHS/2, 256>>>(pos);

    vsplitT_kernel<<<dim3(32,16), 256, VT_SMEM>>>();

    memret_mma_kernel<<<dim3(16,32), 256, 4*MR_TILE + 512>>>(zz);

    attn_mma_kernel<<<dim3(16,32), 256, FTOT>>>();

    m_update_mma_kernel<<<dim3(16,16), 256>>>();
    reduce_m_kernel<<<1024, 256>>>(Mm, out + 8388608);
    reduce_z_kernel<<<8, 256>>>(zz, out + 8388608 + 262144);

    combine_split_kernel<<<MTOT*HIDN/256, 256>>>(beta);
    gemm_mma_kernel<<<dim3(16,32,1), 256, GEMM_SMEM>>>(bq, bk, bv, out, 1);
}